// round 10
// baseline (speedup 1.0000x reference)
#include <cuda_runtime.h>
#include <cuda_fp16.h>
#include <cstdint>

// ---------------------------------------------------------------------------
// PCGen on GB300 (sm_103 baseline ISA): fp16 2-way-split mma.sync GEMMs.
// Tile 128o x 64m, chunk-64 double-buffered cp.async pipeline with ONE
// barrier per chunk, 2 CTAs/SM. BN stats fused into GEMM epilogue.
// B=32, M=2048, CW=512.
// ---------------------------------------------------------------------------

#define BATCH 32
#define MPTS  2048
#define CW    512

// ---------------- scratch (static device memory; no allocs allowed) --------
__device__ float  g_t0 [BATCH * 512 * MPTS];
__device__ float  g_t1 [BATCH * 256 * MPTS];
__device__ float  g_t2 [BATCH * 128 * MPTS];
__device__ float  g_t3 [BATCH * 64  * MPTS];
__device__ float  g_pts[BATCH * 3   * MPTS];
__device__ float  g_aff_a[4 * 512];
__device__ float  g_aff_c[4 * 512];
__device__ float  g_part[2048 * 2 * 512];        // BN partials [part][2*Cout]
__device__ __half g_xnH[BATCH * MPTS * 16],  g_xnL[BATCH * MPTS * 16];
__device__ __half g_y1H[BATCH * MPTS * 256], g_y1L[BATCH * MPTS * 256];
__device__ __half g_y2H[BATCH * MPTS * 512], g_y2L[BATCH * MPTS * 512];
#define NW_TOT 569344
__device__ __half g_WH[NW_TOT], g_WL[NW_TOT];
// weight offsets: L1, L2, c0, c1, c2, c3
#define WO_1 0
#define WO_2 4096
#define WO_3 135168
#define WO_4 397312
#define WO_5 528384
#define WO_6 561152

__device__ __forceinline__ uint32_t smem_u32(const void* p) {
    uint32_t a;
    asm("{ .reg .u64 t; cvta.to.shared.u64 t, %1; cvt.u32.u64 %0, t; }"
        : "=r"(a) : "l"(p));
    return a;
}

#define LDSM4(r0, r1, r2, r3, addr) \
    asm volatile("ldmatrix.sync.aligned.m8n8.x4.shared.b16 {%0,%1,%2,%3}, [%4];" \
                 : "=r"(r0), "=r"(r1), "=r"(r2), "=r"(r3) : "r"(addr))
#define LDSM2(r0, r1, addr) \
    asm volatile("ldmatrix.sync.aligned.m8n8.x2.shared.b16 {%0,%1}, [%2];" \
                 : "=r"(r0), "=r"(r1) : "r"(addr))
#define MMA_FP16(d, a0, a1, a2, a3, b0, b1) \
    asm volatile("mma.sync.aligned.m16n8k16.row.col.f32.f16.f16.f32 " \
                 "{%0,%1,%2,%3}, {%4,%5,%6,%7}, {%8,%9}, {%0,%1,%2,%3};" \
                 : "+f"((d)[0]), "+f"((d)[1]), "+f"((d)[2]), "+f"((d)[3]) \
                 : "r"(a0), "r"(a1), "r"(a2), "r"(a3), "r"(b0), "r"(b1))
#define CP16(saddr, gptr) \
    asm volatile("cp.async.cg.shared.global [%0], [%1], 16;" \
                 :: "r"(saddr), "l"(__cvta_generic_to_global(gptr)))
#define CP_COMMIT() asm volatile("cp.async.commit_group;" ::: "memory")
#define CP_WAIT0()  asm volatile("cp.async.wait_group 0;" ::: "memory")

// ---------------- fused prep: 6 weight splits + sample normalize ------------
__device__ __forceinline__ void wsplit_seg(const float* w, __half* WH,
                                           __half* WL, int n, int blk)
{
    int i = blk * 256 + threadIdx.x;
    if (i >= n) return;
    float v = w[i];
    __half h = __float2half_rn(v);
    WH[i] = h;
    WL[i] = __float2half_rn(v - __half2float(h));
}

__global__ void prep_kernel(const float* __restrict__ w1, const float* __restrict__ w2,
                            const float* __restrict__ w3, const float* __restrict__ w4,
                            const float* __restrict__ w5, const float* __restrict__ w6,
                            __half* __restrict__ WH, __half* __restrict__ WL,
                            const float* __restrict__ s,
                            __half* __restrict__ XH, __half* __restrict__ XL)
{
    int bk = blockIdx.x;
    if (bk < 16)        { wsplit_seg(w1, WH + WO_1, WL + WO_1, 4096,   bk);        return; }
    if (bk < 528)       { wsplit_seg(w2, WH + WO_2, WL + WO_2, 131072, bk - 16);   return; }
    if (bk < 1552)      { wsplit_seg(w3, WH + WO_3, WL + WO_3, 262144, bk - 528);  return; }
    if (bk < 2064)      { wsplit_seg(w4, WH + WO_4, WL + WO_4, 131072, bk - 1552); return; }
    if (bk < 2192)      { wsplit_seg(w5, WH + WO_5, WL + WO_5, 32768,  bk - 2064); return; }
    if (bk < 2224)      { wsplit_seg(w6, WH + WO_6, WL + WO_6, 8192,   bk - 2192); return; }

    // norm_split segment: blocks [2224, 2480)
    int idx = (bk - 2224) * 256 + threadIdx.x;
    int b = idx >> 11, m = idx & (MPTS - 1);
    const float* p = s + (size_t)b * 16 * MPTS + m;
    float v[16]; float ss = 0.f;
#pragma unroll
    for (int c = 0; c < 16; ++c) { v[c] = p[c * MPTS]; ss = fmaf(v[c], v[c], ss); }
    float inv = rsqrtf(ss);
    __half hs[16], ls[16];
#pragma unroll
    for (int c = 0; c < 16; ++c) {
        float f = v[c] * inv;
        hs[c] = __float2half_rn(f);
        ls[c] = __float2half_rn(f - __half2float(hs[c]));
    }
    size_t base = (size_t)idx * 16;
#pragma unroll
    for (int q = 0; q < 2; ++q) {
        *(uint4*)(XH + base + q * 8) = *(uint4*)(hs + q * 8);
        *(uint4*)(XL + base + q * 8) = *(uint4*)(ls + q * 8);
    }
}

// ============ fp16-split tensor GEMM, double-buffered chunk-64 =============
// Y[b][o][m] = sum_k W[o][k] * f(X[b][k][m]) (+bias, epilogue)
// Tile OT x 64m. 256 thr = 8 warps (4o x 2m); warp tile (OT/4) x 32.
// Pipeline per chunk: wait0(stage c) -> sync -> issue(c+1) -> [convert(c+1)]
//                     -> MMA(c).   One barrier per chunk; safe: sync proves
// all warps finished MMA(c-1), so buf[(c+1)&1] (== buf[(c-1)&1]) is free.
// XMODE 0: X pre-split [b][m][Cin] fp16 H/L -> cp.async.
// XMODE 1: X fp32 [b][c][m], f(x)=relu(pa*x+pc), converted into stage.
// EPI 0: fp32 out [b][c][m] + BN partial stats.  EPI 1: relu, split [b][m][c].
// EPI 2: z*clip(v,-1,1), split out [b][m][c].
template <int OT, int XMODE, int EPI>
__global__ __launch_bounds__(256, 2)
void gemm_mma(const __half* __restrict__ XH, const __half* __restrict__ XL,
              const float* __restrict__ Xf,
              const __half* __restrict__ WHg, const __half* __restrict__ WLg,
              const float* __restrict__ bias,
              float* __restrict__ Yf,
              __half* __restrict__ YH, __half* __restrict__ YL,
              int Cin, int Cout,
              const float* __restrict__ pa, const float* __restrict__ pc,
              const float* __restrict__ zmod,
              float* __restrict__ part)
{
    extern __shared__ char smem[];
    constexpr int PITCH = 144;                  // bytes/row (64 fp16 + 8 pad)
    constexpr int OW  = OT / 4;                 // warp o-rows (32 or 16)
    constexpr int OFR = OT / 64;                // 16-row frags per warp (2 or 1)
    constexpr uint32_t OFF_WLO = (uint32_t)OT * PITCH;
    constexpr uint32_t OFF_XHI = 2u * OT * PITCH;
    constexpr uint32_t OFF_XLO = OFF_XHI + 64u * PITCH;
    constexpr uint32_t STAGE   = OFF_XHI + 128u * PITCH;

    const int tid  = threadIdx.x;
    const int lane = tid & 31;
    const int wid  = tid >> 5;
    const int warp_m = wid & 1;                 // 2 m-groups of 32
    const int warp_o = wid >> 1;                // 4 o-groups

    const int b  = blockIdx.z;
    const int m0 = blockIdx.x * 64;
    const int o0 = blockIdx.y * OT;
    const uint32_t sbase = smem_u32(smem);

    float acc[OFR][4][4];
#pragma unroll
    for (int i = 0; i < OFR; ++i)
#pragma unroll
        for (int j = 0; j < 4; ++j)
#pragma unroll
            for (int k = 0; k < 4; ++k) acc[i][j][k] = 0.f;

    const uint32_t aOff = (uint32_t)((warp_o * OW + (lane & 15)) * PITCH
                                     + ((lane >> 4) << 4));
    const uint32_t bOff = OFF_XHI + (uint32_t)((warp_m * 32 + (lane & 7)) * PITCH
                                     + (((lane >> 3) & 1) << 4));

    const int nch = (Cin + 63) >> 6;

    // ---- stage chunk c (W always; X when XMODE==0) via cp.async ----
    auto issue_chunk = [&](int c) {
        const int k0 = c * 64;
        const int kcnt = (Cin - k0 < 64) ? (Cin - k0) : 64;   // 16 or 64
        const int cprsh = (kcnt == 64) ? 3 : 1;
        const int cpr = 1 << cprsh;
        const uint32_t so = sbase + (uint32_t)(c & 1) * STAGE;
        for (int i = tid; i < (OT << cprsh); i += 256) {
            int o = i >> cprsh, p = i & (cpr - 1);
            uint32_t soff = so + (uint32_t)(o * PITCH + p * 16);
            size_t goff = (size_t)(o0 + o) * Cin + k0 + p * 8;
            CP16(soff, WHg + goff);
            CP16(soff + OFF_WLO, WLg + goff);
        }
        if (XMODE == 0) {
            for (int i = tid; i < (64 << cprsh); i += 256) {
                int m = i >> cprsh, p = i & (cpr - 1);
                uint32_t soff = so + OFF_XHI + (uint32_t)(m * PITCH + p * 16);
                size_t goff = ((size_t)b * MPTS + m0 + m) * Cin + k0 + p * 8;
                CP16(soff, XH + goff);
                CP16(soff + 64u * PITCH, XL + goff);
            }
        }
        CP_COMMIT();
    };

    // ---- XMODE 1: convert fp32 chunk c with affine+relu into its stage ----
    auto convert_chunk = [&](int c) {
        const int k0 = c * 64;
        const int kcnt = (Cin - k0 < 64) ? (Cin - k0) : 64;
        const int nq = kcnt >> 2;                             // 4 or 16
        const uint32_t so = (uint32_t)(c & 1) * STAGE;
        char* Xhi = smem + so + OFF_XHI;
        char* Xlo = smem + so + OFF_XLO;
        const float* Xb = Xf + (size_t)b * Cin * MPTS;
        for (int i = tid; i < (nq << 6); i += 256) {
            int m = i & 63, kq = i >> 6;
            int kg = k0 + 4 * kq;
            const float* xp = Xb + (size_t)kg * MPTS + m0 + m;
            float v[4];
#pragma unroll
            for (int j = 0; j < 4; ++j) {
                float t = xp[(size_t)j * MPTS];
                v[j] = fmaxf(fmaf(pa[kg + j], t, pc[kg + j]), 0.f);
            }
            __half h[4]; float r[4];
#pragma unroll
            for (int j = 0; j < 4; ++j) {
                h[j] = __float2half_rn(v[j]);
                r[j] = v[j] - __half2float(h[j]);
            }
            __half2 p0(h[0], h[1]), p1(h[2], h[3]);
            __half2 q0(__float2half_rn(r[0]), __float2half_rn(r[1]));
            __half2 q1(__float2half_rn(r[2]), __float2half_rn(r[3]));
            uint32_t off = (uint32_t)(m * PITCH + kq * 8);
            *(uint2*)(Xhi + off) = make_uint2(*(uint32_t*)&p0, *(uint32_t*)&p1);
            *(uint2*)(Xlo + off) = make_uint2(*(uint32_t*)&q0, *(uint32_t*)&q1);
        }
    };

    // ---- pipeline ----
    issue_chunk(0);
    if (XMODE == 1) convert_chunk(0);

    for (int c = 0; c < nch; ++c) {
        CP_WAIT0();                       // stage(c) landed
        __syncthreads();                  // staging visible; MMA(c-1) done
        if (c + 1 < nch) {
            issue_chunk(c + 1);           // into buf[(c+1)&1], provably free
            if (XMODE == 1) convert_chunk(c + 1);
        }

        const int k0 = c * 64;
        const int kcnt = (Cin - k0 < 64) ? (Cin - k0) : 64;
        const uint32_t so = sbase + (uint32_t)(c & 1) * STAGE;
        const uint32_t aHi = so + aOff;
        const uint32_t aLo = aHi + OFF_WLO;
        const uint32_t bHi = so + bOff;
        const uint32_t bLo = bHi + 64u * PITCH;

        const int ksteps = kcnt >> 4;
        for (int ks = 0; ks < ksteps; ++ks) {
            const uint32_t ko = (uint32_t)ks * 32;
            uint32_t bh[4][2], bl[4][2];
#pragma unroll
            for (int mf = 0; mf < 4; ++mf) {
                LDSM2(bh[mf][0], bh[mf][1], bHi + mf * (8 * PITCH) + ko);
                LDSM2(bl[mf][0], bl[mf][1], bLo + mf * (8 * PITCH) + ko);
            }
#pragma unroll
            for (int of = 0; of < OFR; ++of) {
                uint32_t ah[4], al[4];
                LDSM4(ah[0], ah[1], ah[2], ah[3], aHi + of * (16 * PITCH) + ko);
                LDSM4(al[0], al[1], al[2], al[3], aLo + of * (16 * PITCH) + ko);
#pragma unroll
                for (int mf = 0; mf < 4; ++mf) {
                    MMA_FP16(acc[of][mf], ah[0], ah[1], ah[2], ah[3],
                             bh[mf][0], bh[mf][1]);
                    MMA_FP16(acc[of][mf], al[0], al[1], al[2], al[3],
                             bh[mf][0], bh[mf][1]);
                    MMA_FP16(acc[of][mf], ah[0], ah[1], ah[2], ah[3],
                             bl[mf][0], bl[mf][1]);
                }
            }
        }
    }
    __syncthreads();                      // last MMA done before smem reuse

    if (EPI == 0) {
        // ---- fp32 epilogue + deterministic BN partial stats ----
        float* Yb = Yf + (size_t)b * Cout * MPTS;
        const int prt = (blockIdx.x * 2 + warp_m) * 32 + blockIdx.z; // 0..2047
        float* pbase = part + (size_t)prt * 2 * Cout;
#pragma unroll
        for (int of = 0; of < OFR; ++of) {
            int o = o0 + warp_o * OW + of * 16 + (lane >> 2);
#pragma unroll
            for (int hf = 0; hf < 2; ++hf) {
                int oc = o + hf * 8;
                float bs = bias[oc];
                float s = 0.f, s2 = 0.f;
#pragma unroll
                for (int mf = 0; mf < 4; ++mf) {
                    int m = m0 + warp_m * 32 + mf * 8 + 2 * (lane & 3);
                    float v0 = acc[of][mf][2 * hf]     + bs;
                    float v1 = acc[of][mf][2 * hf + 1] + bs;
                    *(float2*)&Yb[(size_t)oc * MPTS + m] = make_float2(v0, v1);
                    s  += v0 + v1;
                    s2 += v0 * v0 + v1 * v1;
                }
                s  += __shfl_xor_sync(0xffffffffu, s, 1);
                s2 += __shfl_xor_sync(0xffffffffu, s2, 1);
                s  += __shfl_xor_sync(0xffffffffu, s, 2);
                s2 += __shfl_xor_sync(0xffffffffu, s2, 2);
                if ((lane & 3) == 0) {
                    pbase[oc * 2]     = s;
                    pbase[oc * 2 + 1] = s2;
                }
            }
        }
    } else {
        // ---- split epilogue: smem transpose -> [b][m][c] fp16 H/L ----
        constexpr int SP = OT + 8;
        __half* SH = (__half*)smem;                 // 64 x SP
        __half* SL = SH + 64 * SP;
#pragma unroll
        for (int of = 0; of < OFR; ++of) {
            int orel0 = warp_o * OW + of * 16 + (lane >> 2);
#pragma unroll
            for (int hf = 0; hf < 2; ++hf) {
                int orel = orel0 + hf * 8;
                int o = o0 + orel;
                float bs = bias[o];
                float zv = (EPI == 2) ? zmod[(size_t)b * CW + o] : 0.f;
#pragma unroll
                for (int mf = 0; mf < 4; ++mf) {
                    int mrel = warp_m * 32 + mf * 8 + 2 * (lane & 3);
                    float v0 = acc[of][mf][2 * hf]     + bs;
                    float v1 = acc[of][mf][2 * hf + 1] + bs;
                    if (EPI == 1) { v0 = fmaxf(v0, 0.f); v1 = fmaxf(v1, 0.f); }
                    if (EPI == 2) {
                        v0 = zv * fminf(fmaxf(v0, -1.f), 1.f);
                        v1 = zv * fminf(fmaxf(v1, -1.f), 1.f);
                    }
                    __half h0 = __float2half_rn(v0), h1 = __float2half_rn(v1);
                    SH[mrel * SP + orel]       = h0;
                    SH[(mrel + 1) * SP + orel] = h1;
                    SL[mrel * SP + orel]       = __float2half_rn(v0 - __half2float(h0));
                    SL[(mrel + 1) * SP + orel] = __float2half_rn(v1 - __half2float(h1));
                }
            }
        }
        __syncthreads();
        constexpr int CPR = OT / 8;                 // uint4 chunks per m-row
        for (int i = tid; i < 64 * CPR; i += 256) {
            int m = i / CPR, p = i % CPR;
            size_t gb = ((size_t)b * MPTS + m0 + m) * Cout + o0 + p * 8;
            *(uint4*)(YH + gb) = *(uint4*)(SH + m * SP + p * 8);
            *(uint4*)(YL + gb) = *(uint4*)(SL + m * SP + p * 8);
        }
    }
}

// ---------------- BN finalize: partials -> folded affine (a, c) ------------
__global__ void bn_finalize_kernel(const float* __restrict__ part, int Cout,
                                   const float* __restrict__ g,
                                   const float* __restrict__ be,
                                   float* __restrict__ a_out,
                                   float* __restrict__ c_out)
{
    int o = blockIdx.x;
    float s = 0.f, s2 = 0.f;
    for (int p = threadIdx.x; p < 2048; p += 256) {
        const float* pp = part + (size_t)p * 2 * Cout + o * 2;
        s  += pp[0];
        s2 += pp[1];
    }
#pragma unroll
    for (int off = 16; off; off >>= 1) {
        s  += __shfl_down_sync(0xffffffffu, s,  off);
        s2 += __shfl_down_sync(0xffffffffu, s2, off);
    }
    __shared__ float sh[8], sh2[8];
    int w = threadIdx.x >> 5, l = threadIdx.x & 31;
    if (l == 0) { sh[w] = s; sh2[w] = s2; }
    __syncthreads();
    if (threadIdx.x < 8) {
        s = sh[threadIdx.x]; s2 = sh2[threadIdx.x];
#pragma unroll
        for (int off = 4; off; off >>= 1) {
            s  += __shfl_down_sync(0xffu, s,  off);
            s2 += __shfl_down_sync(0xffu, s2, off);
        }
        if (threadIdx.x == 0) {
            const float inv = 1.f / (float)(BATCH * MPTS);
            float mu  = s * inv;
            float var = s2 * inv - mu * mu;
            float aa  = g[o] * rsqrtf(var + 1e-5f);
            a_out[o] = aa;
            c_out[o] = be[o] - aa * mu;
        }
    }
}

// ---------------- final 64->3 projection with folded BN+relu ----------------
__global__ void out_kernel(const float* __restrict__ T3,
                           const float* __restrict__ w_out,
                           const float* __restrict__ b_out,
                           const float* __restrict__ a,
                           const float* __restrict__ c,
                           float* __restrict__ pts)
{
    __shared__ float Ws[3][64];
    __shared__ float As[64], Cs[64];
    int tid = threadIdx.x;
    if (tid < 192) Ws[tid / 64][tid & 63] = w_out[tid];
    if (tid < 64) { As[tid] = a[tid]; Cs[tid] = c[tid]; }
    __syncthreads();

    int idx = blockIdx.x * blockDim.x + tid;
    int b = idx >> 11, m = idx & (MPTS - 1);
    const float* p = T3 + (size_t)b * 64 * MPTS + m;
    float a0 = b_out[0], a1 = b_out[1], a2 = b_out[2];
#pragma unroll 8
    for (int k = 0; k < 64; ++k) {
        float v = fmaxf(fmaf(As[k], p[(size_t)k * MPTS], Cs[k]), 0.f);
        a0 = fmaf(Ws[0][k], v, a0);
        a1 = fmaf(Ws[1][k], v, a1);
        a2 = fmaf(Ws[2][k], v, a2);
    }
    float* q = pts + (size_t)b * 3 * MPTS + m;
    q[0]        = a0;
    q[MPTS]     = a1;
    q[2 * MPTS] = a2;
}

// ---------------- kNN (K=8) sharpening filter -------------------------------
__global__ void graph_filter_kernel(const float* __restrict__ pts,
                                    float* __restrict__ out)
{
    __shared__ float sx[MPTS], sy[MPTS], sz[MPTS], sq[MPTS];
    int b = blockIdx.y;
    int tid = threadIdx.x;
    const float* pb = pts + (size_t)b * 3 * MPTS;
    for (int i = tid; i < MPTS; i += 256) {
        float x = pb[i], y = pb[MPTS + i], z = pb[2 * MPTS + i];
        sx[i] = x; sy[i] = y; sz[i] = z;
        sq[i] = x * x + y * y + z * z;
    }
    __syncthreads();

    int p = blockIdx.x * 256 + tid;
    float px = sx[p], py = sy[p], pz = sz[p];

    float bd[8]; int bi[8];
#pragma unroll
    for (int j = 0; j < 8; ++j) { bd[j] = 3.4e38f; bi[j] = 0; }

#pragma unroll 4
    for (int n = 0; n < MPTS; ++n) {
        float d = sq[n] - 2.f * (px * sx[n] + py * sy[n] + pz * sz[n]);
        if (n != p && d < bd[7]) {
            bd[7] = d; bi[7] = n;
#pragma unroll
            for (int j = 7; j > 0; --j) {
                if (bd[j] < bd[j - 1]) {
                    float td = bd[j]; bd[j] = bd[j - 1]; bd[j - 1] = td;
                    int   ti = bi[j]; bi[j] = bi[j - 1]; bi[j - 1] = ti;
                }
            }
        }
    }

    float mx = 0.f, my = 0.f, mz = 0.f;
#pragma unroll
    for (int j = 0; j < 8; ++j) {
        mx += sx[bi[j]]; my += sy[bi[j]]; mz += sz[bi[j]];
    }
    const float k8 = 1.f / 8.f;
    float* ob = out + (size_t)b * 3 * MPTS;
    ob[p]            = 2.f * px - mx * k8;
    ob[MPTS + p]     = 2.f * py - my * k8;
    ob[2 * MPTS + p] = 2.f * pz - mz * k8;
}

// ---------------------------------------------------------------------------
#define STAGE_OT(OT) ((2 * (OT) + 128) * 144)
#define SMEM_OT(OT)  (2 * STAGE_OT(OT))

extern "C" void kernel_launch(void* const* d_in, const int* in_sizes, int n_in,
                              void* d_out, int out_size)
{
    const float* z     = (const float*)d_in[0];
    const float* s     = (const float*)d_in[1];
    const float* w_m1  = (const float*)d_in[2];
    const float* b_m1  = (const float*)d_in[3];
    const float* w_m2  = (const float*)d_in[4];
    const float* b_m2  = (const float*)d_in[5];
    const float* w_out = (const float*)d_in[6];
    const float* b_out = (const float*)d_in[7];
    const float* w_c [4] = {(const float*)d_in[8],  (const float*)d_in[12],
                            (const float*)d_in[16], (const float*)d_in[20]};
    const float* b_c [4] = {(const float*)d_in[9],  (const float*)d_in[13],
                            (const float*)d_in[17], (const float*)d_in[21]};
    const float* g_c [4] = {(const float*)d_in[10], (const float*)d_in[14],
                            (const float*)d_in[18], (const float*)d_in[22]};
    const float* be_c[4] = {(const float*)d_in[11], (const float*)d_in[15],
                            (const float*)d_in[19], (const float*)d_in[23]};

    float *t0, *t1, *t2, *t3, *pts, *aff_a, *aff_c, *part;
    __half *xnH, *xnL, *y1H, *y1L, *y2H, *y2L, *WH, *WL;
    cudaGetSymbolAddress((void**)&t0,    g_t0);
    cudaGetSymbolAddress((void**)&t1,    g_t1);
    cudaGetSymbolAddress((void**)&t2,    g_t2);
    cudaGetSymbolAddress((void**)&t3,    g_t3);
    cudaGetSymbolAddress((void**)&pts,   g_pts);
    cudaGetSymbolAddress((void**)&aff_a, g_aff_a);
    cudaGetSymbolAddress((void**)&aff_c, g_aff_c);
    cudaGetSymbolAddress((void**)&part,  g_part);
    cudaGetSymbolAddress((void**)&xnH,   g_xnH);
    cudaGetSymbolAddress((void**)&xnL,   g_xnL);
    cudaGetSymbolAddress((void**)&y1H,   g_y1H);
    cudaGetSymbolAddress((void**)&y1L,   g_y1L);
    cudaGetSymbolAddress((void**)&y2H,   g_y2H);
    cudaGetSymbolAddress((void**)&y2L,   g_y2L);
    cudaGetSymbolAddress((void**)&WH,    g_WH);
    cudaGetSymbolAddress((void**)&WL,    g_WL);

    cudaFuncSetAttribute(gemm_mma<128, 0, 1>, cudaFuncAttributeMaxDynamicSharedMemorySize, SMEM_OT(128));
    cudaFuncSetAttribute(gemm_mma<128, 0, 2>, cudaFuncAttributeMaxDynamicSharedMemorySize, SMEM_OT(128));
    cudaFuncSetAttribute(gemm_mma<128, 0, 0>, cudaFuncAttributeMaxDynamicSharedMemorySize, SMEM_OT(128));
    cudaFuncSetAttribute(gemm_mma<128, 1, 0>, cudaFuncAttributeMaxDynamicSharedMemorySize, SMEM_OT(128));
    cudaFuncSetAttribute(gemm_mma<64, 1, 0>,  cudaFuncAttributeMaxDynamicSharedMemorySize, SMEM_OT(64));

    // 0) fused prep: weight splits + sample normalize/split
    prep_kernel<<<2480, 256>>>(w_m1, w_m2, w_c[0], w_c[1], w_c[2], w_c[3],
                               WH, WL, s, xnH, xnL);

    // 1) map_samples1: 16 -> 256, relu, split out
    gemm_mma<128, 0, 1><<<dim3(MPTS / 64, 2, BATCH), 256, SMEM_OT(128)>>>(
        xnH, xnL, nullptr, WH + WO_1, WL + WO_1, b_m1,
        nullptr, y1H, y1L, 16, 256, nullptr, nullptr, nullptr, nullptr);

    // 2) map_samples2: 256 -> 512, z*clip, split out
    gemm_mma<128, 0, 2><<<dim3(MPTS / 64, 4, BATCH), 256, SMEM_OT(128)>>>(
        y1H, y1L, nullptr, WH + WO_2, WL + WO_2, b_m2,
        nullptr, y2H, y2L, 256, 512, nullptr, nullptr, z, nullptr);

    // 3) conv block 0: 512 -> 512, fp32 out + fused stats
    gemm_mma<128, 0, 0><<<dim3(MPTS / 64, 4, BATCH), 256, SMEM_OT(128)>>>(
        y2H, y2L, nullptr, WH + WO_3, WL + WO_3, b_c[0],
        t0, nullptr, nullptr, 512, 512, nullptr, nullptr, nullptr, part);
    bn_finalize_kernel<<<512, 256>>>(part, 512, g_c[0], be_c[0], aff_a, aff_c);

    // 4) conv block 1: relu(bn(t0)) -> 256
    gemm_mma<128, 1, 0><<<dim3(MPTS / 64, 2, BATCH), 256, SMEM_OT(128)>>>(
        nullptr, nullptr, t0, WH + WO_4, WL + WO_4, b_c[1],
        t1, nullptr, nullptr, 512, 256, aff_a, aff_c, nullptr, part);
    bn_finalize_kernel<<<256, 256>>>(part, 256, g_c[1], be_c[1],
                                     aff_a + 512, aff_c + 512);

    // 5) conv block 2: -> 128
    gemm_mma<128, 1, 0><<<dim3(MPTS / 64, 1, BATCH), 256, SMEM_OT(128)>>>(
        nullptr, nullptr, t1, WH + WO_5, WL + WO_5, b_c[2],
        t2, nullptr, nullptr, 256, 128, aff_a + 512, aff_c + 512, nullptr, part);
    bn_finalize_kernel<<<128, 256>>>(part, 128, g_c[2], be_c[2],
                                     aff_a + 1024, aff_c + 1024);

    // 6) conv block 3: -> 64
    gemm_mma<64, 1, 0><<<dim3(MPTS / 64, 1, BATCH), 256, SMEM_OT(64)>>>(
        nullptr, nullptr, t2, WH + WO_6, WL + WO_6, b_c[3],
        t3, nullptr, nullptr, 128, 64, aff_a + 1024, aff_c + 1024, nullptr, part);
    bn_finalize_kernel<<<64, 256>>>(part, 64, g_c[3], be_c[3],
                                    aff_a + 1536, aff_c + 1536);

    // 7) output projection 64 -> 3 (with folded BN+relu)
    out_kernel<<<(BATCH * MPTS) / 256, 256>>>(t3, w_out, b_out,
                                              aff_a + 1536, aff_c + 1536, pts);

    // 8) graph sharpening filter
    graph_filter_kernel<<<dim3(MPTS / 256, BATCH), 256>>>(pts, (float*)d_out);
}

// round 11
// speedup vs baseline: 1.0001x; 1.0001x over previous
#include <cuda_runtime.h>
#include <cuda_fp16.h>
#include <cstdint>

// ---------------------------------------------------------------------------
// PCGen on GB300 (sm_103 baseline ISA): fp16 2-way-split mma.sync GEMMs
// (R9-proven 128x128 serial-chunk mainloop, 2 CTAs/SM), BN stats fused into
// GEMM epilogue (transposed partials), out-projection fused into the kNN
// filter (float4-packed smem, 1 LDS.128 per neighbor).
// B=32, M=2048, CW=512.
// ---------------------------------------------------------------------------

#define BATCH 32
#define MPTS  2048
#define CW    512

// ---------------- scratch (static device memory; no allocs allowed) --------
__device__ float  g_t0 [BATCH * 512 * MPTS];
__device__ float  g_t1 [BATCH * 256 * MPTS];
__device__ float  g_t2 [BATCH * 128 * MPTS];
__device__ float  g_t3 [BATCH * 64  * MPTS];
__device__ float  g_aff_a[4 * 512];
__device__ float  g_aff_c[4 * 512];
__device__ float  g_part[2 * 512 * 2048];        // BN partials [2*oc][part]
__device__ __half g_xnH[BATCH * MPTS * 16],  g_xnL[BATCH * MPTS * 16];
__device__ __half g_y1H[BATCH * MPTS * 256], g_y1L[BATCH * MPTS * 256];
__device__ __half g_y2H[BATCH * MPTS * 512], g_y2L[BATCH * MPTS * 512];
#define NW_TOT 569344
__device__ __half g_WH[NW_TOT], g_WL[NW_TOT];
// weight offsets: L1, L2, c0, c1, c2, c3
#define WO_1 0
#define WO_2 4096
#define WO_3 135168
#define WO_4 397312
#define WO_5 528384
#define WO_6 561152

__device__ __forceinline__ uint32_t smem_u32(const void* p) {
    uint32_t a;
    asm("{ .reg .u64 t; cvta.to.shared.u64 t, %1; cvt.u32.u64 %0, t; }"
        : "=r"(a) : "l"(p));
    return a;
}

#define LDSM4(r0, r1, r2, r3, addr) \
    asm volatile("ldmatrix.sync.aligned.m8n8.x4.shared.b16 {%0,%1,%2,%3}, [%4];" \
                 : "=r"(r0), "=r"(r1), "=r"(r2), "=r"(r3) : "r"(addr))
#define LDSM2(r0, r1, addr) \
    asm volatile("ldmatrix.sync.aligned.m8n8.x2.shared.b16 {%0,%1}, [%2];" \
                 : "=r"(r0), "=r"(r1) : "r"(addr))
#define MMA_FP16(d, a0, a1, a2, a3, b0, b1) \
    asm volatile("mma.sync.aligned.m16n8k16.row.col.f32.f16.f16.f32 " \
                 "{%0,%1,%2,%3}, {%4,%5,%6,%7}, {%8,%9}, {%0,%1,%2,%3};" \
                 : "+f"((d)[0]), "+f"((d)[1]), "+f"((d)[2]), "+f"((d)[3]) \
                 : "r"(a0), "r"(a1), "r"(a2), "r"(a3), "r"(b0), "r"(b1))
#define CP16(saddr, gptr) \
    asm volatile("cp.async.cg.shared.global [%0], [%1], 16;" \
                 :: "r"(saddr), "l"(__cvta_generic_to_global(gptr)))
#define CP_COMMIT() asm volatile("cp.async.commit_group;" ::: "memory")
#define CP_WAIT0()  asm volatile("cp.async.wait_group 0;" ::: "memory")

// ---------------- fused prep: 6 weight splits + sample normalize ------------
__device__ __forceinline__ void wsplit_seg(const float* w, __half* WH,
                                           __half* WL, int n, int blk)
{
    int i = blk * 256 + threadIdx.x;
    if (i >= n) return;
    float v = w[i];
    __half h = __float2half_rn(v);
    WH[i] = h;
    WL[i] = __float2half_rn(v - __half2float(h));
}

__global__ void prep_kernel(const float* __restrict__ w1, const float* __restrict__ w2,
                            const float* __restrict__ w3, const float* __restrict__ w4,
                            const float* __restrict__ w5, const float* __restrict__ w6,
                            __half* __restrict__ WH, __half* __restrict__ WL,
                            const float* __restrict__ s,
                            __half* __restrict__ XH, __half* __restrict__ XL)
{
    int bk = blockIdx.x;
    if (bk < 16)        { wsplit_seg(w1, WH + WO_1, WL + WO_1, 4096,   bk);        return; }
    if (bk < 528)       { wsplit_seg(w2, WH + WO_2, WL + WO_2, 131072, bk - 16);   return; }
    if (bk < 1552)      { wsplit_seg(w3, WH + WO_3, WL + WO_3, 262144, bk - 528);  return; }
    if (bk < 2064)      { wsplit_seg(w4, WH + WO_4, WL + WO_4, 131072, bk - 1552); return; }
    if (bk < 2192)      { wsplit_seg(w5, WH + WO_5, WL + WO_5, 32768,  bk - 2064); return; }
    if (bk < 2224)      { wsplit_seg(w6, WH + WO_6, WL + WO_6, 8192,   bk - 2192); return; }

    // norm_split segment: blocks [2224, 2480)
    int idx = (bk - 2224) * 256 + threadIdx.x;
    int b = idx >> 11, m = idx & (MPTS - 1);
    const float* p = s + (size_t)b * 16 * MPTS + m;
    float v[16]; float ss = 0.f;
#pragma unroll
    for (int c = 0; c < 16; ++c) { v[c] = p[c * MPTS]; ss = fmaf(v[c], v[c], ss); }
    float inv = rsqrtf(ss);
    __half hs[16], ls[16];
#pragma unroll
    for (int c = 0; c < 16; ++c) {
        float f = v[c] * inv;
        hs[c] = __float2half_rn(f);
        ls[c] = __float2half_rn(f - __half2float(hs[c]));
    }
    size_t base = (size_t)idx * 16;
#pragma unroll
    for (int q = 0; q < 2; ++q) {
        *(uint4*)(XH + base + q * 8) = *(uint4*)(hs + q * 8);
        *(uint4*)(XL + base + q * 8) = *(uint4*)(ls + q * 8);
    }
}

// ============ fp16-split tensor GEMM (R9 mainloop) =========================
// Y[b][o][m] = sum_k W[o][k] * f(X[b][k][m]) (+bias, epilogue)
// OT: out-channels/block. Block: 256 thr = 8 warps (2o x 4m); warp OT/2 x 32.
// XMODE 0: X pre-split [b][m][Cin] fp16 H/L -> cp.async copy staging.
// XMODE 1: X fp32 [b][c][m], f(x)=relu(pa*x+pc) fused, split at staging.
// EPI 0: fp32 out [b][c][m] + BN partial stats.  EPI 1: relu, split [b][m][c].
// EPI 2: z*clip(v,-1,1), split out [b][m][c].
template <int OT, int XMODE, int EPI>
__global__ __launch_bounds__(256, 2)
void gemm_mma(const __half* __restrict__ XH, const __half* __restrict__ XL,
              const float* __restrict__ Xf,
              const __half* __restrict__ WHg, const __half* __restrict__ WLg,
              const float* __restrict__ bias,
              float* __restrict__ Yf,
              __half* __restrict__ YH, __half* __restrict__ YL,
              int Cin, int Cout,
              const float* __restrict__ pa, const float* __restrict__ pc,
              const float* __restrict__ zmod,
              float* __restrict__ part)
{
    extern __shared__ char smem[];
    constexpr int PITCH = 144;            // bytes/row (64 fp16 + 8 pad)
    constexpr int OW  = OT / 2;
    constexpr int OFR = OT / 32;
    char* Whi = smem;
    char* Wlo = smem + OT * PITCH;
    char* Xhi = smem + 2 * OT * PITCH;
    char* Xlo = Xhi + 128 * PITCH;

    const int tid  = threadIdx.x;
    const int lane = tid & 31;
    const int wid  = tid >> 5;
    const int warp_m = wid & 3;
    const int warp_o = wid >> 2;

    const int b  = blockIdx.z;
    const int m0 = blockIdx.x * 128;
    const int o0 = blockIdx.y * OT;

    float acc[OFR][4][4];
#pragma unroll
    for (int i = 0; i < OFR; ++i)
#pragma unroll
        for (int j = 0; j < 4; ++j)
#pragma unroll
            for (int k = 0; k < 4; ++k) acc[i][j][k] = 0.f;

    const uint32_t aHi = smem_u32(Whi) + (warp_o * OW + (lane & 15)) * PITCH
                       + ((lane >> 4) << 4);
    const uint32_t aLo = aHi + OT * PITCH;
    const uint32_t bHi = smem_u32(Xhi) + (warp_m * 32 + (lane & 7)) * PITCH
                       + (((lane >> 3) & 1) << 4);
    const uint32_t bLo = bHi + 128 * PITCH;
    const uint32_t sWhi = smem_u32(Whi);
    const uint32_t sXhi = smem_u32(Xhi);

    for (int k0 = 0; k0 < Cin; k0 += 64) {
        const int kcnt = (Cin - k0 < 64) ? (Cin - k0) : 64;     // 16 or 64
        const int cprsh = (kcnt == 64) ? 3 : 1;
        const int cpr   = 1 << cprsh;

        for (int i = tid; i < (OT << cprsh); i += 256) {
            int o = i >> cprsh, p = i & (cpr - 1);
            uint32_t soff = sWhi + (uint32_t)(o * PITCH + p * 16);
            size_t goff = (size_t)(o0 + o) * Cin + k0 + p * 8;
            CP16(soff, WHg + goff);
            CP16(soff + (uint32_t)OT * PITCH, WLg + goff);
        }

        if (XMODE == 0) {
            for (int i = tid; i < (128 << cprsh); i += 256) {
                int m = i >> cprsh, p = i & (cpr - 1);
                uint32_t soff = sXhi + (uint32_t)(m * PITCH + p * 16);
                size_t goff = ((size_t)b * MPTS + m0 + m) * Cin + k0 + p * 8;
                CP16(soff, XH + goff);
                CP16(soff + 128u * PITCH, XL + goff);
            }
            CP_COMMIT(); CP_WAIT0();
        } else {
            CP_COMMIT();
            const float* Xb = Xf + (size_t)b * Cin * MPTS;
            const int nq = kcnt >> 2;
            for (int i = tid; i < (nq << 7); i += 256) {
                int m = i & 127, kq = i >> 7;
                int kg = k0 + 4 * kq;
                const float* xp = Xb + (size_t)kg * MPTS + m0 + m;
                float v[4];
#pragma unroll
                for (int j = 0; j < 4; ++j) {
                    float t = xp[(size_t)j * MPTS];
                    v[j] = fmaxf(fmaf(pa[kg + j], t, pc[kg + j]), 0.f);
                }
                __half h[4]; float r[4];
#pragma unroll
                for (int j = 0; j < 4; ++j) {
                    h[j] = __float2half_rn(v[j]);
                    r[j] = v[j] - __half2float(h[j]);
                }
                __half2 p0(h[0], h[1]), p1(h[2], h[3]);
                __half2 q0(__float2half_rn(r[0]), __float2half_rn(r[1]));
                __half2 q1(__float2half_rn(r[2]), __float2half_rn(r[3]));
                uint32_t off = (uint32_t)(m * PITCH + kq * 8);
                *(uint2*)(Xhi + off) = make_uint2(*(uint32_t*)&p0, *(uint32_t*)&p1);
                *(uint2*)(Xlo + off) = make_uint2(*(uint32_t*)&q0, *(uint32_t*)&q1);
            }
            CP_WAIT0();
        }
        __syncthreads();

        const int ksteps = kcnt >> 4;
        for (int ks = 0; ks < ksteps; ++ks) {
            const uint32_t ko = (uint32_t)ks * 32;
            uint32_t bh[4][2], bl[4][2];
#pragma unroll
            for (int mf = 0; mf < 4; ++mf) {
                LDSM2(bh[mf][0], bh[mf][1], bHi + mf * (8 * PITCH) + ko);
                LDSM2(bl[mf][0], bl[mf][1], bLo + mf * (8 * PITCH) + ko);
            }
#pragma unroll
            for (int of = 0; of < OFR; ++of) {
                uint32_t ah[4], al[4];
                LDSM4(ah[0], ah[1], ah[2], ah[3], aHi + of * (16 * PITCH) + ko);
                LDSM4(al[0], al[1], al[2], al[3], aLo + of * (16 * PITCH) + ko);
#pragma unroll
                for (int mf = 0; mf < 4; ++mf) {
                    MMA_FP16(acc[of][mf], ah[0], ah[1], ah[2], ah[3],
                             bh[mf][0], bh[mf][1]);
                    MMA_FP16(acc[of][mf], al[0], al[1], al[2], al[3],
                             bh[mf][0], bh[mf][1]);
                    MMA_FP16(acc[of][mf], ah[0], ah[1], ah[2], ah[3],
                             bl[mf][0], bl[mf][1]);
                }
            }
        }
        __syncthreads();
    }

    if (EPI == 0) {
        // ---- fp32 epilogue + deterministic BN partial stats ----
        float* Yb = Yf + (size_t)b * Cout * MPTS;
        const int prt = (blockIdx.x * 4 + warp_m) * 32 + blockIdx.z; // 0..2047
#pragma unroll
        for (int of = 0; of < OFR; ++of) {
            int o = o0 + warp_o * OW + of * 16 + (lane >> 2);
#pragma unroll
            for (int hf = 0; hf < 2; ++hf) {
                int oc = o + hf * 8;
                float bs = bias[oc];
                float s = 0.f, s2 = 0.f;
#pragma unroll
                for (int mf = 0; mf < 4; ++mf) {
                    int m = m0 + warp_m * 32 + mf * 8 + 2 * (lane & 3);
                    float v0 = acc[of][mf][2 * hf]     + bs;
                    float v1 = acc[of][mf][2 * hf + 1] + bs;
                    *(float2*)&Yb[(size_t)oc * MPTS + m] = make_float2(v0, v1);
                    s  += v0 + v1;
                    s2 += v0 * v0 + v1 * v1;
                }
                s  += __shfl_xor_sync(0xffffffffu, s, 1);
                s2 += __shfl_xor_sync(0xffffffffu, s2, 1);
                s  += __shfl_xor_sync(0xffffffffu, s, 2);
                s2 += __shfl_xor_sync(0xffffffffu, s2, 2);
                if ((lane & 3) == 0) {
                    // transposed partials: coalesced reads in finalize
                    part[(size_t)(2 * oc)     * 2048 + prt] = s;
                    part[(size_t)(2 * oc + 1) * 2048 + prt] = s2;
                }
            }
        }
    } else {
        // ---- split epilogue: smem transpose -> [b][m][c] fp16 H/L ----
        __half* SH = (__half*)smem;                 // 128 x 136
        __half* SL = SH + 128 * 136;
#pragma unroll
        for (int of = 0; of < OFR; ++of) {
            int orel0 = warp_o * OW + of * 16 + (lane >> 2);
#pragma unroll
            for (int hf = 0; hf < 2; ++hf) {
                int orel = orel0 + hf * 8;
                int o = o0 + orel;
                float bs = bias[o];
                float zv = (EPI == 2) ? zmod[(size_t)b * CW + o] : 0.f;
#pragma unroll
                for (int mf = 0; mf < 4; ++mf) {
                    int mrel = warp_m * 32 + mf * 8 + 2 * (lane & 3);
                    float v0 = acc[of][mf][2 * hf]     + bs;
                    float v1 = acc[of][mf][2 * hf + 1] + bs;
                    if (EPI == 1) { v0 = fmaxf(v0, 0.f); v1 = fmaxf(v1, 0.f); }
                    if (EPI == 2) {
                        v0 = zv * fminf(fmaxf(v0, -1.f), 1.f);
                        v1 = zv * fminf(fmaxf(v1, -1.f), 1.f);
                    }
                    __half h0 = __float2half_rn(v0), h1 = __float2half_rn(v1);
                    SH[mrel * 136 + orel]       = h0;
                    SH[(mrel + 1) * 136 + orel] = h1;
                    SL[mrel * 136 + orel]       = __float2half_rn(v0 - __half2float(h0));
                    SL[(mrel + 1) * 136 + orel] = __float2half_rn(v1 - __half2float(h1));
                }
            }
        }
        __syncthreads();
        for (int i = tid; i < 2048; i += 256) {
            int m = i >> 4, p = i & 15;
            size_t gb = ((size_t)b * MPTS + m0 + m) * Cout + o0 + p * 8;
            *(uint4*)(YH + gb) = *(uint4*)(SH + m * 136 + p * 8);
            *(uint4*)(YL + gb) = *(uint4*)(SL + m * 136 + p * 8);
        }
    }
}

// ---------------- BN finalize: partials -> folded affine (a, c) ------------
__global__ void bn_finalize_kernel(const float* __restrict__ part, int Cout,
                                   const float* __restrict__ g,
                                   const float* __restrict__ be,
                                   float* __restrict__ a_out,
                                   float* __restrict__ c_out)
{
    int o = blockIdx.x;
    const float* ps  = part + (size_t)(2 * o)     * 2048;
    const float* ps2 = part + (size_t)(2 * o + 1) * 2048;
    float s = 0.f, s2 = 0.f;
    for (int p = threadIdx.x; p < 2048; p += 256) {
        s  += ps[p];
        s2 += ps2[p];
    }
#pragma unroll
    for (int off = 16; off; off >>= 1) {
        s  += __shfl_down_sync(0xffffffffu, s,  off);
        s2 += __shfl_down_sync(0xffffffffu, s2, off);
    }
    __shared__ float sh[8], sh2[8];
    int w = threadIdx.x >> 5, l = threadIdx.x & 31;
    if (l == 0) { sh[w] = s; sh2[w] = s2; }
    __syncthreads();
    if (threadIdx.x < 8) {
        s = sh[threadIdx.x]; s2 = sh2[threadIdx.x];
#pragma unroll
        for (int off = 4; off; off >>= 1) {
            s  += __shfl_down_sync(0xffu, s,  off);
            s2 += __shfl_down_sync(0xffu, s2, off);
        }
        if (threadIdx.x == 0) {
            const float inv = 1.f / (float)(BATCH * MPTS);
            float mu  = s * inv;
            float var = s2 * inv - mu * mu;
            float aa  = g[o] * rsqrtf(var + 1e-5f);
            a_out[o] = aa;
            c_out[o] = be[o] - aa * mu;
        }
    }
}

// ---------------- fused out-projection + kNN (K=8) sharpening filter -------
// Each block (chunk, b): recompute ALL 2048 points of batch b from t3 (64ch,
// folded BN+relu + 64->3 projection), pack (x,y,z,|p|^2) into float4 smem,
// then kNN top-8 + sharpening for its 256 points.
__global__ __launch_bounds__(256, 2)
void filter_fused_kernel(const float* __restrict__ T3,
                         const float* __restrict__ w_out,
                         const float* __restrict__ b_out,
                         const float* __restrict__ a,
                         const float* __restrict__ c,
                         float* __restrict__ out)
{
    __shared__ __align__(16) float4 pk[MPTS];
    __shared__ float Ws[3][64];
    __shared__ float As[64], Cs[64];
    int b = blockIdx.y;
    int tid = threadIdx.x;
    if (tid < 192) Ws[tid / 64][tid & 63] = w_out[tid];
    if (tid < 64) { As[tid] = a[tid]; Cs[tid] = c[tid]; }
    __syncthreads();

    const float* Tb = T3 + (size_t)b * 64 * MPTS;
    float ob0 = b_out[0], ob1 = b_out[1], ob2 = b_out[2];
    for (int m = tid; m < MPTS; m += 256) {
        const float* p = Tb + m;
        float a0 = ob0, a1 = ob1, a2 = ob2;
#pragma unroll 8
        for (int k = 0; k < 64; ++k) {
            float v = fmaxf(fmaf(As[k], p[(size_t)k * MPTS], Cs[k]), 0.f);
            a0 = fmaf(Ws[0][k], v, a0);
            a1 = fmaf(Ws[1][k], v, a1);
            a2 = fmaf(Ws[2][k], v, a2);
        }
        pk[m] = make_float4(a0, a1, a2,
                            a0 * a0 + a1 * a1 + a2 * a2);
    }
    __syncthreads();

    int p = blockIdx.x * 256 + tid;
    float4 me = pk[p];
    float nx = -2.f * me.x, ny = -2.f * me.y, nz = -2.f * me.z;

    float bd[8]; int bi[8];
#pragma unroll
    for (int j = 0; j < 8; ++j) { bd[j] = 3.4e38f; bi[j] = 0; }

    for (int n = 0; n < MPTS; ++n) {
        float4 q = pk[n];
        float d = fmaf(nx, q.x, fmaf(ny, q.y, fmaf(nz, q.z, q.w)));
        if (n != p && d < bd[7]) {
            bd[7] = d; bi[7] = n;
#pragma unroll
            for (int j = 7; j > 0; --j) {
                if (bd[j] < bd[j - 1]) {
                    float td = bd[j]; bd[j] = bd[j - 1]; bd[j - 1] = td;
                    int   ti = bi[j]; bi[j] = bi[j - 1]; bi[j - 1] = ti;
                }
            }
        }
    }

    float mx = 0.f, my = 0.f, mz = 0.f;
#pragma unroll
    for (int j = 0; j < 8; ++j) {
        float4 q = pk[bi[j]];
        mx += q.x; my += q.y; mz += q.z;
    }
    const float k8 = 1.f / 8.f;
    float* ob = out + (size_t)b * 3 * MPTS;
    ob[p]            = 2.f * me.x - mx * k8;
    ob[MPTS + p]     = 2.f * me.y - my * k8;
    ob[2 * MPTS + p] = 2.f * me.z - mz * k8;
}

// ---------------------------------------------------------------------------
#define SMEM128 (4 * 128 * 144)
#define SMEM64  (2 * 64 * 144 + 2 * 128 * 144)

extern "C" void kernel_launch(void* const* d_in, const int* in_sizes, int n_in,
                              void* d_out, int out_size)
{
    const float* z     = (const float*)d_in[0];
    const float* s     = (const float*)d_in[1];
    const float* w_m1  = (const float*)d_in[2];
    const float* b_m1  = (const float*)d_in[3];
    const float* w_m2  = (const float*)d_in[4];
    const float* b_m2  = (const float*)d_in[5];
    const float* w_out = (const float*)d_in[6];
    const float* b_out = (const float*)d_in[7];
    const float* w_c [4] = {(const float*)d_in[8],  (const float*)d_in[12],
                            (const float*)d_in[16], (const float*)d_in[20]};
    const float* b_c [4] = {(const float*)d_in[9],  (const float*)d_in[13],
                            (const float*)d_in[17], (const float*)d_in[21]};
    const float* g_c [4] = {(const float*)d_in[10], (const float*)d_in[14],
                            (const float*)d_in[18], (const float*)d_in[22]};
    const float* be_c[4] = {(const float*)d_in[11], (const float*)d_in[15],
                            (const float*)d_in[19], (const float*)d_in[23]};

    float *t0, *t1, *t2, *t3, *aff_a, *aff_c, *part;
    __half *xnH, *xnL, *y1H, *y1L, *y2H, *y2L, *WH, *WL;
    cudaGetSymbolAddress((void**)&t0,    g_t0);
    cudaGetSymbolAddress((void**)&t1,    g_t1);
    cudaGetSymbolAddress((void**)&t2,    g_t2);
    cudaGetSymbolAddress((void**)&t3,    g_t3);
    cudaGetSymbolAddress((void**)&aff_a, g_aff_a);
    cudaGetSymbolAddress((void**)&aff_c, g_aff_c);
    cudaGetSymbolAddress((void**)&part,  g_part);
    cudaGetSymbolAddress((void**)&xnH,   g_xnH);
    cudaGetSymbolAddress((void**)&xnL,   g_xnL);
    cudaGetSymbolAddress((void**)&y1H,   g_y1H);
    cudaGetSymbolAddress((void**)&y1L,   g_y1L);
    cudaGetSymbolAddress((void**)&y2H,   g_y2H);
    cudaGetSymbolAddress((void**)&y2L,   g_y2L);
    cudaGetSymbolAddress((void**)&WH,    g_WH);
    cudaGetSymbolAddress((void**)&WL,    g_WL);

    cudaFuncSetAttribute(gemm_mma<128, 0, 1>, cudaFuncAttributeMaxDynamicSharedMemorySize, SMEM128);
    cudaFuncSetAttribute(gemm_mma<128, 0, 2>, cudaFuncAttributeMaxDynamicSharedMemorySize, SMEM128);
    cudaFuncSetAttribute(gemm_mma<128, 0, 0>, cudaFuncAttributeMaxDynamicSharedMemorySize, SMEM128);
    cudaFuncSetAttribute(gemm_mma<128, 1, 0>, cudaFuncAttributeMaxDynamicSharedMemorySize, SMEM128);
    cudaFuncSetAttribute(gemm_mma<64, 1, 0>,  cudaFuncAttributeMaxDynamicSharedMemorySize, SMEM64);

    // 0) fused prep: weight splits + sample normalize/split
    prep_kernel<<<2480, 256>>>(w_m1, w_m2, w_c[0], w_c[1], w_c[2], w_c[3],
                               WH, WL, s, xnH, xnL);

    // 1) map_samples1: 16 -> 256, relu, split out
    gemm_mma<128, 0, 1><<<dim3(MPTS / 128, 2, BATCH), 256, SMEM128>>>(
        xnH, xnL, nullptr, WH + WO_1, WL + WO_1, b_m1,
        nullptr, y1H, y1L, 16, 256, nullptr, nullptr, nullptr, nullptr);

    // 2) map_samples2: 256 -> 512, z*clip, split out
    gemm_mma<128, 0, 2><<<dim3(MPTS / 128, 4, BATCH), 256, SMEM128>>>(
        y1H, y1L, nullptr, WH + WO_2, WL + WO_2, b_m2,
        nullptr, y2H, y2L, 256, 512, nullptr, nullptr, z, nullptr);

    // 3) conv block 0: 512 -> 512, fp32 out + fused stats
    gemm_mma<128, 0, 0><<<dim3(MPTS / 128, 4, BATCH), 256, SMEM128>>>(
        y2H, y2L, nullptr, WH + WO_3, WL + WO_3, b_c[0],
        t0, nullptr, nullptr, 512, 512, nullptr, nullptr, nullptr, part);
    bn_finalize_kernel<<<512, 256>>>(part, 512, g_c[0], be_c[0], aff_a, aff_c);

    // 4) conv block 1: relu(bn(t0)) -> 256
    gemm_mma<128, 1, 0><<<dim3(MPTS / 128, 2, BATCH), 256, SMEM128>>>(
        nullptr, nullptr, t0, WH + WO_4, WL + WO_4, b_c[1],
        t1, nullptr, nullptr, 512, 256, aff_a, aff_c, nullptr, part);
    bn_finalize_kernel<<<256, 256>>>(part, 256, g_c[1], be_c[1],
                                     aff_a + 512, aff_c + 512);

    // 5) conv block 2: -> 128
    gemm_mma<128, 1, 0><<<dim3(MPTS / 128, 1, BATCH), 256, SMEM128>>>(
        nullptr, nullptr, t1, WH + WO_5, WL + WO_5, b_c[2],
        t2, nullptr, nullptr, 256, 128, aff_a + 512, aff_c + 512, nullptr, part);
    bn_finalize_kernel<<<128, 256>>>(part, 128, g_c[2], be_c[2],
                                     aff_a + 1024, aff_c + 1024);

    // 6) conv block 3: -> 64
    gemm_mma<64, 1, 0><<<dim3(MPTS / 128, 1, BATCH), 256, SMEM64>>>(
        nullptr, nullptr, t2, WH + WO_6, WL + WO_6, b_c[3],
        t3, nullptr, nullptr, 128, 64, aff_a + 1024, aff_c + 1024, nullptr, part);
    bn_finalize_kernel<<<64, 256>>>(part, 64, g_c[3], be_c[3],
                                    aff_a + 1536, aff_c + 1536);

    // 7) fused out-projection + graph sharpening filter
    filter_fused_kernel<<<dim3(MPTS / 256, BATCH), 256>>>(
        t3, w_out, b_out, aff_a + 1536, aff_c + 1536, (float*)d_out);
}

// round 12
// speedup vs baseline: 1.0150x; 1.0149x over previous
#include <cuda_runtime.h>
#include <cuda_fp16.h>
#include <cstdint>

// ---------------------------------------------------------------------------
// PCGen on GB300 (sm_103 baseline ISA): fp16 2-way-split mma.sync GEMMs
// (R9-proven 128x128 serial-chunk mainloop, 2 CTAs/SM), BN stats fused into
// GEMM epilogue (transposed partials), out-projection writes packed float4
// (x,y,z,|p|^2), kNN filter with LDS.128 neighbors + 2-way unroll.
// B=32, M=2048, CW=512.
// ---------------------------------------------------------------------------

#define BATCH 32
#define MPTS  2048
#define CW    512

// ---------------- scratch (static device memory; no allocs allowed) --------
__device__ float  g_t0 [BATCH * 512 * MPTS];
__device__ float  g_t1 [BATCH * 256 * MPTS];
__device__ float  g_t2 [BATCH * 128 * MPTS];
__device__ float  g_t3 [BATCH * 64  * MPTS];
__device__ float4 g_pk [BATCH * MPTS];           // packed (x,y,z,|p|^2)
__device__ float  g_aff_a[4 * 512];
__device__ float  g_aff_c[4 * 512];
__device__ float  g_part[2 * 512 * 2048];        // BN partials [2*oc][part]
__device__ __half g_xnH[BATCH * MPTS * 16],  g_xnL[BATCH * MPTS * 16];
__device__ __half g_y1H[BATCH * MPTS * 256], g_y1L[BATCH * MPTS * 256];
__device__ __half g_y2H[BATCH * MPTS * 512], g_y2L[BATCH * MPTS * 512];
#define NW_TOT 569344
__device__ __half g_WH[NW_TOT], g_WL[NW_TOT];
// weight offsets: L1, L2, c0, c1, c2, c3
#define WO_1 0
#define WO_2 4096
#define WO_3 135168
#define WO_4 397312
#define WO_5 528384
#define WO_6 561152

__device__ __forceinline__ uint32_t smem_u32(const void* p) {
    uint32_t a;
    asm("{ .reg .u64 t; cvta.to.shared.u64 t, %1; cvt.u32.u64 %0, t; }"
        : "=r"(a) : "l"(p));
    return a;
}

#define LDSM4(r0, r1, r2, r3, addr) \
    asm volatile("ldmatrix.sync.aligned.m8n8.x4.shared.b16 {%0,%1,%2,%3}, [%4];" \
                 : "=r"(r0), "=r"(r1), "=r"(r2), "=r"(r3) : "r"(addr))
#define LDSM2(r0, r1, addr) \
    asm volatile("ldmatrix.sync.aligned.m8n8.x2.shared.b16 {%0,%1}, [%2];" \
                 : "=r"(r0), "=r"(r1) : "r"(addr))
#define MMA_FP16(d, a0, a1, a2, a3, b0, b1) \
    asm volatile("mma.sync.aligned.m16n8k16.row.col.f32.f16.f16.f32 " \
                 "{%0,%1,%2,%3}, {%4,%5,%6,%7}, {%8,%9}, {%0,%1,%2,%3};" \
                 : "+f"((d)[0]), "+f"((d)[1]), "+f"((d)[2]), "+f"((d)[3]) \
                 : "r"(a0), "r"(a1), "r"(a2), "r"(a3), "r"(b0), "r"(b1))
#define CP16(saddr, gptr) \
    asm volatile("cp.async.cg.shared.global [%0], [%1], 16;" \
                 :: "r"(saddr), "l"(__cvta_generic_to_global(gptr)))
#define CP_COMMIT() asm volatile("cp.async.commit_group;" ::: "memory")
#define CP_WAIT0()  asm volatile("cp.async.wait_group 0;" ::: "memory")

// ---------------- fused prep: 6 weight splits + sample normalize ------------
__device__ __forceinline__ void wsplit_seg(const float* w, __half* WH,
                                           __half* WL, int n, int blk)
{
    int i = blk * 256 + threadIdx.x;
    if (i >= n) return;
    float v = w[i];
    __half h = __float2half_rn(v);
    WH[i] = h;
    WL[i] = __float2half_rn(v - __half2float(h));
}

__global__ void prep_kernel(const float* __restrict__ w1, const float* __restrict__ w2,
                            const float* __restrict__ w3, const float* __restrict__ w4,
                            const float* __restrict__ w5, const float* __restrict__ w6,
                            __half* __restrict__ WH, __half* __restrict__ WL,
                            const float* __restrict__ s,
                            __half* __restrict__ XH, __half* __restrict__ XL)
{
    int bk = blockIdx.x;
    if (bk < 16)        { wsplit_seg(w1, WH + WO_1, WL + WO_1, 4096,   bk);        return; }
    if (bk < 528)       { wsplit_seg(w2, WH + WO_2, WL + WO_2, 131072, bk - 16);   return; }
    if (bk < 1552)      { wsplit_seg(w3, WH + WO_3, WL + WO_3, 262144, bk - 528);  return; }
    if (bk < 2064)      { wsplit_seg(w4, WH + WO_4, WL + WO_4, 131072, bk - 1552); return; }
    if (bk < 2192)      { wsplit_seg(w5, WH + WO_5, WL + WO_5, 32768,  bk - 2064); return; }
    if (bk < 2224)      { wsplit_seg(w6, WH + WO_6, WL + WO_6, 8192,   bk - 2192); return; }

    // norm_split segment: blocks [2224, 2480)
    int idx = (bk - 2224) * 256 + threadIdx.x;
    int b = idx >> 11, m = idx & (MPTS - 1);
    const float* p = s + (size_t)b * 16 * MPTS + m;
    float v[16]; float ss = 0.f;
#pragma unroll
    for (int c = 0; c < 16; ++c) { v[c] = p[c * MPTS]; ss = fmaf(v[c], v[c], ss); }
    float inv = rsqrtf(ss);
    __half hs[16], ls[16];
#pragma unroll
    for (int c = 0; c < 16; ++c) {
        float f = v[c] * inv;
        hs[c] = __float2half_rn(f);
        ls[c] = __float2half_rn(f - __half2float(hs[c]));
    }
    size_t base = (size_t)idx * 16;
#pragma unroll
    for (int q = 0; q < 2; ++q) {
        *(uint4*)(XH + base + q * 8) = *(uint4*)(hs + q * 8);
        *(uint4*)(XL + base + q * 8) = *(uint4*)(ls + q * 8);
    }
}

// ============ fp16-split tensor GEMM (R9 mainloop) =========================
// Y[b][o][m] = sum_k W[o][k] * f(X[b][k][m]) (+bias, epilogue)
// OT: out-channels/block. Block: 256 thr = 8 warps (2o x 4m); warp OT/2 x 32.
// XMODE 0: X pre-split [b][m][Cin] fp16 H/L -> cp.async copy staging.
// XMODE 1: X fp32 [b][c][m], f(x)=relu(pa*x+pc) fused, split at staging.
// EPI 0: fp32 out [b][c][m] + BN partial stats.  EPI 1: relu, split [b][m][c].
// EPI 2: z*clip(v,-1,1), split out [b][m][c].
template <int OT, int XMODE, int EPI>
__global__ __launch_bounds__(256, 2)
void gemm_mma(const __half* __restrict__ XH, const __half* __restrict__ XL,
              const float* __restrict__ Xf,
              const __half* __restrict__ WHg, const __half* __restrict__ WLg,
              const float* __restrict__ bias,
              float* __restrict__ Yf,
              __half* __restrict__ YH, __half* __restrict__ YL,
              int Cin, int Cout,
              const float* __restrict__ pa, const float* __restrict__ pc,
              const float* __restrict__ zmod,
              float* __restrict__ part)
{
    extern __shared__ char smem[];
    constexpr int PITCH = 144;            // bytes/row (64 fp16 + 8 pad)
    constexpr int OW  = OT / 2;
    constexpr int OFR = OT / 32;
    char* Whi = smem;
    char* Wlo = smem + OT * PITCH;
    char* Xhi = smem + 2 * OT * PITCH;
    char* Xlo = Xhi + 128 * PITCH;

    const int tid  = threadIdx.x;
    const int lane = tid & 31;
    const int wid  = tid >> 5;
    const int warp_m = wid & 3;
    const int warp_o = wid >> 2;

    const int b  = blockIdx.z;
    const int m0 = blockIdx.x * 128;
    const int o0 = blockIdx.y * OT;

    float acc[OFR][4][4];
#pragma unroll
    for (int i = 0; i < OFR; ++i)
#pragma unroll
        for (int j = 0; j < 4; ++j)
#pragma unroll
            for (int k = 0; k < 4; ++k) acc[i][j][k] = 0.f;

    const uint32_t aHi = smem_u32(Whi) + (warp_o * OW + (lane & 15)) * PITCH
                       + ((lane >> 4) << 4);
    const uint32_t aLo = aHi + OT * PITCH;
    const uint32_t bHi = smem_u32(Xhi) + (warp_m * 32 + (lane & 7)) * PITCH
                       + (((lane >> 3) & 1) << 4);
    const uint32_t bLo = bHi + 128 * PITCH;
    const uint32_t sWhi = smem_u32(Whi);
    const uint32_t sXhi = smem_u32(Xhi);

    for (int k0 = 0; k0 < Cin; k0 += 64) {
        const int kcnt = (Cin - k0 < 64) ? (Cin - k0) : 64;     // 16 or 64
        const int cprsh = (kcnt == 64) ? 3 : 1;
        const int cpr   = 1 << cprsh;

        for (int i = tid; i < (OT << cprsh); i += 256) {
            int o = i >> cprsh, p = i & (cpr - 1);
            uint32_t soff = sWhi + (uint32_t)(o * PITCH + p * 16);
            size_t goff = (size_t)(o0 + o) * Cin + k0 + p * 8;
            CP16(soff, WHg + goff);
            CP16(soff + (uint32_t)OT * PITCH, WLg + goff);
        }

        if (XMODE == 0) {
            for (int i = tid; i < (128 << cprsh); i += 256) {
                int m = i >> cprsh, p = i & (cpr - 1);
                uint32_t soff = sXhi + (uint32_t)(m * PITCH + p * 16);
                size_t goff = ((size_t)b * MPTS + m0 + m) * Cin + k0 + p * 8;
                CP16(soff, XH + goff);
                CP16(soff + 128u * PITCH, XL + goff);
            }
            CP_COMMIT(); CP_WAIT0();
        } else {
            CP_COMMIT();
            const float* Xb = Xf + (size_t)b * Cin * MPTS;
            const int nq = kcnt >> 2;
            for (int i = tid; i < (nq << 7); i += 256) {
                int m = i & 127, kq = i >> 7;
                int kg = k0 + 4 * kq;
                const float* xp = Xb + (size_t)kg * MPTS + m0 + m;
                float v[4];
#pragma unroll
                for (int j = 0; j < 4; ++j) {
                    float t = xp[(size_t)j * MPTS];
                    v[j] = fmaxf(fmaf(pa[kg + j], t, pc[kg + j]), 0.f);
                }
                __half h[4]; float r[4];
#pragma unroll
                for (int j = 0; j < 4; ++j) {
                    h[j] = __float2half_rn(v[j]);
                    r[j] = v[j] - __half2float(h[j]);
                }
                __half2 p0(h[0], h[1]), p1(h[2], h[3]);
                __half2 q0(__float2half_rn(r[0]), __float2half_rn(r[1]));
                __half2 q1(__float2half_rn(r[2]), __float2half_rn(r[3]));
                uint32_t off = (uint32_t)(m * PITCH + kq * 8);
                *(uint2*)(Xhi + off) = make_uint2(*(uint32_t*)&p0, *(uint32_t*)&p1);
                *(uint2*)(Xlo + off) = make_uint2(*(uint32_t*)&q0, *(uint32_t*)&q1);
            }
            CP_WAIT0();
        }
        __syncthreads();

        const int ksteps = kcnt >> 4;
        for (int ks = 0; ks < ksteps; ++ks) {
            const uint32_t ko = (uint32_t)ks * 32;
            uint32_t bh[4][2], bl[4][2];
#pragma unroll
            for (int mf = 0; mf < 4; ++mf) {
                LDSM2(bh[mf][0], bh[mf][1], bHi + mf * (8 * PITCH) + ko);
                LDSM2(bl[mf][0], bl[mf][1], bLo + mf * (8 * PITCH) + ko);
            }
#pragma unroll
            for (int of = 0; of < OFR; ++of) {
                uint32_t ah[4], al[4];
                LDSM4(ah[0], ah[1], ah[2], ah[3], aHi + of * (16 * PITCH) + ko);
                LDSM4(al[0], al[1], al[2], al[3], aLo + of * (16 * PITCH) + ko);
#pragma unroll
                for (int mf = 0; mf < 4; ++mf) {
                    MMA_FP16(acc[of][mf], ah[0], ah[1], ah[2], ah[3],
                             bh[mf][0], bh[mf][1]);
                    MMA_FP16(acc[of][mf], al[0], al[1], al[2], al[3],
                             bh[mf][0], bh[mf][1]);
                    MMA_FP16(acc[of][mf], ah[0], ah[1], ah[2], ah[3],
                             bl[mf][0], bl[mf][1]);
                }
            }
        }
        __syncthreads();
    }

    if (EPI == 0) {
        // ---- fp32 epilogue + deterministic BN partial stats ----
        float* Yb = Yf + (size_t)b * Cout * MPTS;
        const int prt = (blockIdx.x * 4 + warp_m) * 32 + blockIdx.z; // 0..2047
#pragma unroll
        for (int of = 0; of < OFR; ++of) {
            int o = o0 + warp_o * OW + of * 16 + (lane >> 2);
#pragma unroll
            for (int hf = 0; hf < 2; ++hf) {
                int oc = o + hf * 8;
                float bs = bias[oc];
                float s = 0.f, s2 = 0.f;
#pragma unroll
                for (int mf = 0; mf < 4; ++mf) {
                    int m = m0 + warp_m * 32 + mf * 8 + 2 * (lane & 3);
                    float v0 = acc[of][mf][2 * hf]     + bs;
                    float v1 = acc[of][mf][2 * hf + 1] + bs;
                    *(float2*)&Yb[(size_t)oc * MPTS + m] = make_float2(v0, v1);
                    s  += v0 + v1;
                    s2 += v0 * v0 + v1 * v1;
                }
                s  += __shfl_xor_sync(0xffffffffu, s, 1);
                s2 += __shfl_xor_sync(0xffffffffu, s2, 1);
                s  += __shfl_xor_sync(0xffffffffu, s, 2);
                s2 += __shfl_xor_sync(0xffffffffu, s2, 2);
                if ((lane & 3) == 0) {
                    part[(size_t)(2 * oc)     * 2048 + prt] = s;
                    part[(size_t)(2 * oc + 1) * 2048 + prt] = s2;
                }
            }
        }
    } else {
        // ---- split epilogue: smem transpose -> [b][m][c] fp16 H/L ----
        __half* SH = (__half*)smem;                 // 128 x 136
        __half* SL = SH + 128 * 136;
#pragma unroll
        for (int of = 0; of < OFR; ++of) {
            int orel0 = warp_o * OW + of * 16 + (lane >> 2);
#pragma unroll
            for (int hf = 0; hf < 2; ++hf) {
                int orel = orel0 + hf * 8;
                int o = o0 + orel;
                float bs = bias[o];
                float zv = (EPI == 2) ? zmod[(size_t)b * CW + o] : 0.f;
#pragma unroll
                for (int mf = 0; mf < 4; ++mf) {
                    int mrel = warp_m * 32 + mf * 8 + 2 * (lane & 3);
                    float v0 = acc[of][mf][2 * hf]     + bs;
                    float v1 = acc[of][mf][2 * hf + 1] + bs;
                    if (EPI == 1) { v0 = fmaxf(v0, 0.f); v1 = fmaxf(v1, 0.f); }
                    if (EPI == 2) {
                        v0 = zv * fminf(fmaxf(v0, -1.f), 1.f);
                        v1 = zv * fminf(fmaxf(v1, -1.f), 1.f);
                    }
                    __half h0 = __float2half_rn(v0), h1 = __float2half_rn(v1);
                    SH[mrel * 136 + orel]       = h0;
                    SH[(mrel + 1) * 136 + orel] = h1;
                    SL[mrel * 136 + orel]       = __float2half_rn(v0 - __half2float(h0));
                    SL[(mrel + 1) * 136 + orel] = __float2half_rn(v1 - __half2float(h1));
                }
            }
        }
        __syncthreads();
        for (int i = tid; i < 2048; i += 256) {
            int m = i >> 4, p = i & 15;
            size_t gb = ((size_t)b * MPTS + m0 + m) * Cout + o0 + p * 8;
            *(uint4*)(YH + gb) = *(uint4*)(SH + m * 136 + p * 8);
            *(uint4*)(YL + gb) = *(uint4*)(SL + m * 136 + p * 8);
        }
    }
}

// ---------------- BN finalize: partials -> folded affine (a, c) ------------
__global__ void bn_finalize_kernel(const float* __restrict__ part, int Cout,
                                   const float* __restrict__ g,
                                   const float* __restrict__ be,
                                   float* __restrict__ a_out,
                                   float* __restrict__ c_out)
{
    int o = blockIdx.x;
    const float* ps  = part + (size_t)(2 * o)     * 2048;
    const float* ps2 = part + (size_t)(2 * o + 1) * 2048;
    float s = 0.f, s2 = 0.f;
    for (int p = threadIdx.x; p < 2048; p += 256) {
        s  += ps[p];
        s2 += ps2[p];
    }
#pragma unroll
    for (int off = 16; off; off >>= 1) {
        s  += __shfl_down_sync(0xffffffffu, s,  off);
        s2 += __shfl_down_sync(0xffffffffu, s2, off);
    }
    __shared__ float sh[8], sh2[8];
    int w = threadIdx.x >> 5, l = threadIdx.x & 31;
    if (l == 0) { sh[w] = s; sh2[w] = s2; }
    __syncthreads();
    if (threadIdx.x < 8) {
        s = sh[threadIdx.x]; s2 = sh2[threadIdx.x];
#pragma unroll
        for (int off = 4; off; off >>= 1) {
            s  += __shfl_down_sync(0xffu, s,  off);
            s2 += __shfl_down_sync(0xffu, s2, off);
        }
        if (threadIdx.x == 0) {
            const float inv = 1.f / (float)(BATCH * MPTS);
            float mu  = s * inv;
            float var = s2 * inv - mu * mu;
            float aa  = g[o] * rsqrtf(var + 1e-5f);
            a_out[o] = aa;
            c_out[o] = be[o] - aa * mu;
        }
    }
}

// ---------------- 64->3 projection -> packed float4 (x,y,z,|p|^2) ----------
__global__ void out_kernel(const float* __restrict__ T3,
                           const float* __restrict__ w_out,
                           const float* __restrict__ b_out,
                           const float* __restrict__ a,
                           const float* __restrict__ c,
                           float4* __restrict__ pk)
{
    __shared__ float Ws[3][64];
    __shared__ float As[64], Cs[64];
    int tid = threadIdx.x;
    if (tid < 192) Ws[tid / 64][tid & 63] = w_out[tid];
    if (tid < 64) { As[tid] = a[tid]; Cs[tid] = c[tid]; }
    __syncthreads();

    int idx = blockIdx.x * blockDim.x + tid;
    int b = idx >> 11, m = idx & (MPTS - 1);
    const float* p = T3 + (size_t)b * 64 * MPTS + m;
    float a0 = b_out[0], a1 = b_out[1], a2 = b_out[2];
#pragma unroll 8
    for (int k = 0; k < 64; ++k) {
        float v = fmaxf(fmaf(As[k], p[(size_t)k * MPTS], Cs[k]), 0.f);
        a0 = fmaf(Ws[0][k], v, a0);
        a1 = fmaf(Ws[1][k], v, a1);
        a2 = fmaf(Ws[2][k], v, a2);
    }
    pk[idx] = make_float4(a0, a1, a2, a0 * a0 + a1 * a1 + a2 * a2);
}

// ---------------- kNN (K=8) sharpening filter (float4 smem, unroll 2) -------
__global__ __launch_bounds__(256, 2)
void graph_filter_kernel(const float4* __restrict__ pk_g,
                         float* __restrict__ out)
{
    __shared__ __align__(16) float4 pk[MPTS];
    int b = blockIdx.y;
    int tid = threadIdx.x;
    const float4* pb = pk_g + (size_t)b * MPTS;
    for (int i = tid; i < MPTS; i += 256)
        pk[i] = pb[i];
    __syncthreads();

    int p = blockIdx.x * 256 + tid;
    float4 me = pk[p];
    float nx = -2.f * me.x, ny = -2.f * me.y, nz = -2.f * me.z;

    float bd[8]; int bi[8];
#pragma unroll
    for (int j = 0; j < 8; ++j) { bd[j] = 3.4e38f; bi[j] = 0; }

    for (int n = 0; n < MPTS; n += 2) {
        float4 q0 = pk[n];
        float4 q1 = pk[n + 1];
        float d0 = fmaf(nx, q0.x, fmaf(ny, q0.y, fmaf(nz, q0.z, q0.w)));
        float d1 = fmaf(nx, q1.x, fmaf(ny, q1.y, fmaf(nz, q1.z, q1.w)));
        if (n != p && d0 < bd[7]) {
            bd[7] = d0; bi[7] = n;
#pragma unroll
            for (int j = 7; j > 0; --j)
                if (bd[j] < bd[j - 1]) {
                    float td = bd[j]; bd[j] = bd[j - 1]; bd[j - 1] = td;
                    int   ti = bi[j]; bi[j] = bi[j - 1]; bi[j - 1] = ti;
                }
        }
        if (n + 1 != p && d1 < bd[7]) {
            bd[7] = d1; bi[7] = n + 1;
#pragma unroll
            for (int j = 7; j > 0; --j)
                if (bd[j] < bd[j - 1]) {
                    float td = bd[j]; bd[j] = bd[j - 1]; bd[j - 1] = td;
                    int   ti = bi[j]; bi[j] = bi[j - 1]; bi[j - 1] = ti;
                }
        }
    }

    float mx = 0.f, my = 0.f, mz = 0.f;
#pragma unroll
    for (int j = 0; j < 8; ++j) {
        float4 q = pk[bi[j]];
        mx += q.x; my += q.y; mz += q.z;
    }
    const float k8 = 1.f / 8.f;
    float* ob = out + (size_t)b * 3 * MPTS;
    ob[p]            = 2.f * me.x - mx * k8;
    ob[MPTS + p]     = 2.f * me.y - my * k8;
    ob[2 * MPTS + p] = 2.f * me.z - mz * k8;
}

// ---------------------------------------------------------------------------
#define SMEM128 (4 * 128 * 144)
#define SMEM64  (2 * 64 * 144 + 2 * 128 * 144)

extern "C" void kernel_launch(void* const* d_in, const int* in_sizes, int n_in,
                              void* d_out, int out_size)
{
    const float* z     = (const float*)d_in[0];
    const float* s     = (const float*)d_in[1];
    const float* w_m1  = (const float*)d_in[2];
    const float* b_m1  = (const float*)d_in[3];
    const float* w_m2  = (const float*)d_in[4];
    const float* b_m2  = (const float*)d_in[5];
    const float* w_out = (const float*)d_in[6];
    const float* b_out = (const float*)d_in[7];
    const float* w_c [4] = {(const float*)d_in[8],  (const float*)d_in[12],
                            (const float*)d_in[16], (const float*)d_in[20]};
    const float* b_c [4] = {(const float*)d_in[9],  (const float*)d_in[13],
                            (const float*)d_in[17], (const float*)d_in[21]};
    const float* g_c [4] = {(const float*)d_in[10], (const float*)d_in[14],
                            (const float*)d_in[18], (const float*)d_in[22]};
    const float* be_c[4] = {(const float*)d_in[11], (const float*)d_in[15],
                            (const float*)d_in[19], (const float*)d_in[23]};

    float *t0, *t1, *t2, *t3, *aff_a, *aff_c, *part;
    float4* pk;
    __half *xnH, *xnL, *y1H, *y1L, *y2H, *y2L, *WH, *WL;
    cudaGetSymbolAddress((void**)&t0,    g_t0);
    cudaGetSymbolAddress((void**)&t1,    g_t1);
    cudaGetSymbolAddress((void**)&t2,    g_t2);
    cudaGetSymbolAddress((void**)&t3,    g_t3);
    cudaGetSymbolAddress((void**)&pk,    g_pk);
    cudaGetSymbolAddress((void**)&aff_a, g_aff_a);
    cudaGetSymbolAddress((void**)&aff_c, g_aff_c);
    cudaGetSymbolAddress((void**)&part,  g_part);
    cudaGetSymbolAddress((void**)&xnH,   g_xnH);
    cudaGetSymbolAddress((void**)&xnL,   g_xnL);
    cudaGetSymbolAddress((void**)&y1H,   g_y1H);
    cudaGetSymbolAddress((void**)&y1L,   g_y1L);
    cudaGetSymbolAddress((void**)&y2H,   g_y2H);
    cudaGetSymbolAddress((void**)&y2L,   g_y2L);
    cudaGetSymbolAddress((void**)&WH,    g_WH);
    cudaGetSymbolAddress((void**)&WL,    g_WL);

    cudaFuncSetAttribute(gemm_mma<128, 0, 1>, cudaFuncAttributeMaxDynamicSharedMemorySize, SMEM128);
    cudaFuncSetAttribute(gemm_mma<128, 0, 2>, cudaFuncAttributeMaxDynamicSharedMemorySize, SMEM128);
    cudaFuncSetAttribute(gemm_mma<128, 0, 0>, cudaFuncAttributeMaxDynamicSharedMemorySize, SMEM128);
    cudaFuncSetAttribute(gemm_mma<128, 1, 0>, cudaFuncAttributeMaxDynamicSharedMemorySize, SMEM128);
    cudaFuncSetAttribute(gemm_mma<64, 1, 0>,  cudaFuncAttributeMaxDynamicSharedMemorySize, SMEM64);

    // 0) fused prep: weight splits + sample normalize/split
    prep_kernel<<<2480, 256>>>(w_m1, w_m2, w_c[0], w_c[1], w_c[2], w_c[3],
                               WH, WL, s, xnH, xnL);

    // 1) map_samples1: 16 -> 256, relu, split out
    gemm_mma<128, 0, 1><<<dim3(MPTS / 128, 2, BATCH), 256, SMEM128>>>(
        xnH, xnL, nullptr, WH + WO_1, WL + WO_1, b_m1,
        nullptr, y1H, y1L, 16, 256, nullptr, nullptr, nullptr, nullptr);

    // 2) map_samples2: 256 -> 512, z*clip, split out
    gemm_mma<128, 0, 2><<<dim3(MPTS / 128, 4, BATCH), 256, SMEM128>>>(
        y1H, y1L, nullptr, WH + WO_2, WL + WO_2, b_m2,
        nullptr, y2H, y2L, 256, 512, nullptr, nullptr, z, nullptr);

    // 3) conv block 0: 512 -> 512, fp32 out + fused stats
    gemm_mma<128, 0, 0><<<dim3(MPTS / 128, 4, BATCH), 256, SMEM128>>>(
        y2H, y2L, nullptr, WH + WO_3, WL + WO_3, b_c[0],
        t0, nullptr, nullptr, 512, 512, nullptr, nullptr, nullptr, part);
    bn_finalize_kernel<<<512, 256>>>(part, 512, g_c[0], be_c[0], aff_a, aff_c);

    // 4) conv block 1: relu(bn(t0)) -> 256
    gemm_mma<128, 1, 0><<<dim3(MPTS / 128, 2, BATCH), 256, SMEM128>>>(
        nullptr, nullptr, t0, WH + WO_4, WL + WO_4, b_c[1],
        t1, nullptr, nullptr, 512, 256, aff_a, aff_c, nullptr, part);
    bn_finalize_kernel<<<256, 256>>>(part, 256, g_c[1], be_c[1],
                                     aff_a + 512, aff_c + 512);

    // 5) conv block 2: -> 128
    gemm_mma<128, 1, 0><<<dim3(MPTS / 128, 1, BATCH), 256, SMEM128>>>(
        nullptr, nullptr, t1, WH + WO_5, WL + WO_5, b_c[2],
        t2, nullptr, nullptr, 256, 128, aff_a + 512, aff_c + 512, nullptr, part);
    bn_finalize_kernel<<<128, 256>>>(part, 128, g_c[2], be_c[2],
                                     aff_a + 1024, aff_c + 1024);

    // 6) conv block 3: -> 64
    gemm_mma<64, 1, 0><<<dim3(MPTS / 128, 1, BATCH), 256, SMEM64>>>(
        nullptr, nullptr, t2, WH + WO_6, WL + WO_6, b_c[3],
        t3, nullptr, nullptr, 128, 64, aff_a + 1024, aff_c + 1024, nullptr, part);
    bn_finalize_kernel<<<64, 256>>>(part, 64, g_c[3], be_c[3],
                                    aff_a + 1536, aff_c + 1536);

    // 7) output projection 64 -> 3 -> packed float4
    out_kernel<<<(BATCH * MPTS) / 256, 256>>>(t3, w_out, b_out,
                                              aff_a + 1536, aff_c + 1536, pk);

    // 8) graph sharpening filter
    graph_filter_kernel<<<dim3(MPTS / 256, BATCH), 256>>>(pk, (float*)d_out);
}

// round 13
// speedup vs baseline: 1.0234x; 1.0083x over previous
#include <cuda_runtime.h>
#include <cuda_fp16.h>
#include <cstdint>

// ---------------------------------------------------------------------------
// PCGen on GB300 (sm_103 baseline ISA): fp16 2-way-split mma.sync GEMMs.
// Tile 128o x 128m, chunk-32 (PITCH 80) double-buffered cp.async pipeline,
// ONE barrier per chunk, 2 CTAs/SM. BN stats fused into GEMM epilogue.
// Out-projection writes packed float4; kNN filter LDS.128 + 2-way unroll.
// B=32, M=2048, CW=512.
// ---------------------------------------------------------------------------

#define BATCH 32
#define MPTS  2048
#define CW    512

// ---------------- scratch (static device memory; no allocs allowed) --------
__device__ float  g_t0 [BATCH * 512 * MPTS];
__device__ float  g_t1 [BATCH * 256 * MPTS];
__device__ float  g_t2 [BATCH * 128 * MPTS];
__device__ float  g_t3 [BATCH * 64  * MPTS];
__device__ float4 g_pk [BATCH * MPTS];           // packed (x,y,z,|p|^2)
__device__ float  g_aff_a[4 * 512];
__device__ float  g_aff_c[4 * 512];
__device__ float  g_part[2 * 512 * 2048];        // BN partials [2*oc][part]
__device__ __half g_xnH[BATCH * MPTS * 16],  g_xnL[BATCH * MPTS * 16];
__device__ __half g_y1H[BATCH * MPTS * 256], g_y1L[BATCH * MPTS * 256];
__device__ __half g_y2H[BATCH * MPTS * 512], g_y2L[BATCH * MPTS * 512];
#define NW_TOT 569344
__device__ __half g_WH[NW_TOT], g_WL[NW_TOT];
// weight offsets: L1, L2, c0, c1, c2, c3
#define WO_1 0
#define WO_2 4096
#define WO_3 135168
#define WO_4 397312
#define WO_5 528384
#define WO_6 561152

__device__ __forceinline__ uint32_t smem_u32(const void* p) {
    uint32_t a;
    asm("{ .reg .u64 t; cvta.to.shared.u64 t, %1; cvt.u32.u64 %0, t; }"
        : "=r"(a) : "l"(p));
    return a;
}

#define LDSM4(r0, r1, r2, r3, addr) \
    asm volatile("ldmatrix.sync.aligned.m8n8.x4.shared.b16 {%0,%1,%2,%3}, [%4];" \
                 : "=r"(r0), "=r"(r1), "=r"(r2), "=r"(r3) : "r"(addr))
#define LDSM2(r0, r1, addr) \
    asm volatile("ldmatrix.sync.aligned.m8n8.x2.shared.b16 {%0,%1}, [%2];" \
                 : "=r"(r0), "=r"(r1) : "r"(addr))
#define MMA_FP16(d, a0, a1, a2, a3, b0, b1) \
    asm volatile("mma.sync.aligned.m16n8k16.row.col.f32.f16.f16.f32 " \
                 "{%0,%1,%2,%3}, {%4,%5,%6,%7}, {%8,%9}, {%0,%1,%2,%3};" \
                 : "+f"((d)[0]), "+f"((d)[1]), "+f"((d)[2]), "+f"((d)[3]) \
                 : "r"(a0), "r"(a1), "r"(a2), "r"(a3), "r"(b0), "r"(b1))
#define CP16(saddr, gptr) \
    asm volatile("cp.async.cg.shared.global [%0], [%1], 16;" \
                 :: "r"(saddr), "l"(__cvta_generic_to_global(gptr)))
#define CP_COMMIT() asm volatile("cp.async.commit_group;" ::: "memory")
#define CP_WAIT0()  asm volatile("cp.async.wait_group 0;" ::: "memory")

// ---------------- fused prep: 6 weight splits + sample normalize ------------
__device__ __forceinline__ void wsplit_seg(const float* w, __half* WH,
                                           __half* WL, int n, int blk)
{
    int i = blk * 256 + threadIdx.x;
    if (i >= n) return;
    float v = w[i];
    __half h = __float2half_rn(v);
    WH[i] = h;
    WL[i] = __float2half_rn(v - __half2float(h));
}

__global__ void prep_kernel(const float* __restrict__ w1, const float* __restrict__ w2,
                            const float* __restrict__ w3, const float* __restrict__ w4,
                            const float* __restrict__ w5, const float* __restrict__ w6,
                            __half* __restrict__ WH, __half* __restrict__ WL,
                            const float* __restrict__ s,
                            __half* __restrict__ XH, __half* __restrict__ XL)
{
    int bk = blockIdx.x;
    if (bk < 16)        { wsplit_seg(w1, WH + WO_1, WL + WO_1, 4096,   bk);        return; }
    if (bk < 528)       { wsplit_seg(w2, WH + WO_2, WL + WO_2, 131072, bk - 16);   return; }
    if (bk < 1552)      { wsplit_seg(w3, WH + WO_3, WL + WO_3, 262144, bk - 528);  return; }
    if (bk < 2064)      { wsplit_seg(w4, WH + WO_4, WL + WO_4, 131072, bk - 1552); return; }
    if (bk < 2192)      { wsplit_seg(w5, WH + WO_5, WL + WO_5, 32768,  bk - 2064); return; }
    if (bk < 2224)      { wsplit_seg(w6, WH + WO_6, WL + WO_6, 8192,   bk - 2192); return; }

    // norm_split segment: blocks [2224, 2480)
    int idx = (bk - 2224) * 256 + threadIdx.x;
    int b = idx >> 11, m = idx & (MPTS - 1);
    const float* p = s + (size_t)b * 16 * MPTS + m;
    float v[16]; float ss = 0.f;
#pragma unroll
    for (int c = 0; c < 16; ++c) { v[c] = p[c * MPTS]; ss = fmaf(v[c], v[c], ss); }
    float inv = rsqrtf(ss);
    __half hs[16], ls[16];
#pragma unroll
    for (int c = 0; c < 16; ++c) {
        float f = v[c] * inv;
        hs[c] = __float2half_rn(f);
        ls[c] = __float2half_rn(f - __half2float(hs[c]));
    }
    size_t base = (size_t)idx * 16;
#pragma unroll
    for (int q = 0; q < 2; ++q) {
        *(uint4*)(XH + base + q * 8) = *(uint4*)(hs + q * 8);
        *(uint4*)(XL + base + q * 8) = *(uint4*)(ls + q * 8);
    }
}

// ============ fp16-split tensor GEMM, chunk-32 double-buffered =============
// Y[b][o][m] = sum_k W[o][k] * f(X[b][k][m]) (+bias, epilogue)
// Tile OT x 128m. 256 thr = 8 warps (2o x 4m); warp tile (OT/2) x 32.
// Chunk 32 channels, PITCH 80 (R8-verified banking). Two stages:
//   loop c: wait0 -> sync -> issue(c+1)[/convert(c+1)] -> MMA(c)
// Race-free: the sync proves MMA(c-1) done, so buf[(c+1)&1] is free; the
// cp.async for c+1 overlaps the whole MMA(c) phase.
// XMODE 0: X pre-split [b][m][Cin] fp16 H/L -> cp.async.
// XMODE 1: X fp32 [b][c][m], f(x)=relu(pa*x+pc), converted into stage.
// EPI 0: fp32 out [b][c][m] + BN partial stats.  EPI 1: relu, split [b][m][c].
// EPI 2: z*clip(v,-1,1), split out [b][m][c].
template <int OT, int XMODE, int EPI>
__global__ __launch_bounds__(256, 2)
void gemm_mma(const __half* __restrict__ XH, const __half* __restrict__ XL,
              const float* __restrict__ Xf,
              const __half* __restrict__ WHg, const __half* __restrict__ WLg,
              const float* __restrict__ bias,
              float* __restrict__ Yf,
              __half* __restrict__ YH, __half* __restrict__ YL,
              int Cin, int Cout,
              const float* __restrict__ pa, const float* __restrict__ pc,
              const float* __restrict__ zmod,
              float* __restrict__ part)
{
    extern __shared__ char smem[];
    constexpr int PITCH = 80;                   // 32 fp16 + 16B pad
    constexpr int OW  = OT / 2;
    constexpr int OFR = OT / 32;
    constexpr uint32_t OFF_WLO = (uint32_t)OT * PITCH;
    constexpr uint32_t OFF_XHI = 2u * OT * PITCH;
    constexpr uint32_t OFF_XLO = OFF_XHI + 128u * PITCH;
    constexpr uint32_t STAGE   = OFF_XHI + 2u * 128u * PITCH;

    const int tid  = threadIdx.x;
    const int lane = tid & 31;
    const int wid  = tid >> 5;
    const int warp_m = wid & 3;
    const int warp_o = wid >> 2;

    const int b  = blockIdx.z;
    const int m0 = blockIdx.x * 128;
    const int o0 = blockIdx.y * OT;
    const uint32_t sbase = smem_u32(smem);

    float acc[OFR][4][4];
#pragma unroll
    for (int i = 0; i < OFR; ++i)
#pragma unroll
        for (int j = 0; j < 4; ++j)
#pragma unroll
            for (int k = 0; k < 4; ++k) acc[i][j][k] = 0.f;

    const uint32_t aOff = (uint32_t)((warp_o * OW + (lane & 15)) * PITCH
                                     + ((lane >> 4) << 4));
    const uint32_t bOff = OFF_XHI + (uint32_t)((warp_m * 32 + (lane & 7)) * PITCH
                                     + (((lane >> 3) & 1) << 4));

    const int nch = (Cin + 31) >> 5;

    // ---- stage chunk c (W always; X when XMODE==0) via cp.async ----
    auto issue_chunk = [&](int c) {
        const int k0 = c * 32;
        const int kcnt = (Cin - k0 < 32) ? (Cin - k0) : 32;   // 16 or 32
        const int cprsh = (kcnt == 32) ? 2 : 1;               // 16B chunks/row
        const int cpr = 1 << cprsh;
        const uint32_t so = sbase + (uint32_t)(c & 1) * STAGE;
        for (int i = tid; i < (OT << cprsh); i += 256) {
            int o = i >> cprsh, p = i & (cpr - 1);
            uint32_t soff = so + (uint32_t)(o * PITCH + p * 16);
            size_t goff = (size_t)(o0 + o) * Cin + k0 + p * 8;
            CP16(soff, WHg + goff);
            CP16(soff + OFF_WLO, WLg + goff);
        }
        if (XMODE == 0) {
            for (int i = tid; i < (128 << cprsh); i += 256) {
                int m = i >> cprsh, p = i & (cpr - 1);
                uint32_t soff = so + OFF_XHI + (uint32_t)(m * PITCH + p * 16);
                size_t goff = ((size_t)b * MPTS + m0 + m) * Cin + k0 + p * 8;
                CP16(soff, XH + goff);
                CP16(soff + 128u * PITCH, XL + goff);
            }
        }
        CP_COMMIT();
    };

    // ---- XMODE 1: convert fp32 chunk c with affine+relu into its stage ----
    auto convert_chunk = [&](int c) {
        const int k0 = c * 32;
        const int kcnt = (Cin - k0 < 32) ? (Cin - k0) : 32;
        const int nq = kcnt >> 2;                             // 4 or 8
        const uint32_t so = (uint32_t)(c & 1) * STAGE;
        char* Xhi = smem + so + OFF_XHI;
        char* Xlo = smem + so + OFF_XLO;
        const float* Xb = Xf + (size_t)b * Cin * MPTS;
        for (int i = tid; i < (nq << 7); i += 256) {
            int m = i & 127, kq = i >> 7;
            int kg = k0 + 4 * kq;
            const float* xp = Xb + (size_t)kg * MPTS + m0 + m;
            float v[4];
#pragma unroll
            for (int j = 0; j < 4; ++j) {
                float t = xp[(size_t)j * MPTS];
                v[j] = fmaxf(fmaf(pa[kg + j], t, pc[kg + j]), 0.f);
            }
            __half h[4]; float r[4];
#pragma unroll
            for (int j = 0; j < 4; ++j) {
                h[j] = __float2half_rn(v[j]);
                r[j] = v[j] - __half2float(h[j]);
            }
            __half2 p0(h[0], h[1]), p1(h[2], h[3]);
            __half2 q0(__float2half_rn(r[0]), __float2half_rn(r[1]));
            __half2 q1(__float2half_rn(r[2]), __float2half_rn(r[3]));
            uint32_t off = (uint32_t)(m * PITCH + kq * 8);
            *(uint2*)(Xhi + off) = make_uint2(*(uint32_t*)&p0, *(uint32_t*)&p1);
            *(uint2*)(Xlo + off) = make_uint2(*(uint32_t*)&q0, *(uint32_t*)&q1);
        }
    };

    // ---- pipeline ----
    issue_chunk(0);
    if (XMODE == 1) convert_chunk(0);

    for (int c = 0; c < nch; ++c) {
        CP_WAIT0();                       // stage(c) cp.async landed
        __syncthreads();                  // staging visible; MMA(c-1) done
        if (c + 1 < nch) {
            issue_chunk(c + 1);           // overlaps MMA(c)
            if (XMODE == 1) convert_chunk(c + 1);
        }

        const int k0 = c * 32;
        const int kcnt = (Cin - k0 < 32) ? (Cin - k0) : 32;
        const uint32_t so = sbase + (uint32_t)(c & 1) * STAGE;
        const uint32_t aHi = so + aOff;
        const uint32_t aLo = aHi + OFF_WLO;
        const uint32_t bHi = so + bOff;
        const uint32_t bLo = bHi + 128u * PITCH;

        const int ksteps = kcnt >> 4;                         // 1 or 2
        for (int ks = 0; ks < ksteps; ++ks) {
            const uint32_t ko = (uint32_t)ks * 32;
            uint32_t bh[4][2], bl[4][2];
#pragma unroll
            for (int mf = 0; mf < 4; ++mf) {
                LDSM2(bh[mf][0], bh[mf][1], bHi + mf * (8 * PITCH) + ko);
                LDSM2(bl[mf][0], bl[mf][1], bLo + mf * (8 * PITCH) + ko);
            }
#pragma unroll
            for (int of = 0; of < OFR; ++of) {
                uint32_t ah[4], al[4];
                LDSM4(ah[0], ah[1], ah[2], ah[3], aHi + of * (16 * PITCH) + ko);
                LDSM4(al[0], al[1], al[2], al[3], aLo + of * (16 * PITCH) + ko);
#pragma unroll
                for (int mf = 0; mf < 4; ++mf) {
                    MMA_FP16(acc[of][mf], ah[0], ah[1], ah[2], ah[3],
                             bh[mf][0], bh[mf][1]);
                    MMA_FP16(acc[of][mf], al[0], al[1], al[2], al[3],
                             bh[mf][0], bh[mf][1]);
                    MMA_FP16(acc[of][mf], ah[0], ah[1], ah[2], ah[3],
                             bl[mf][0], bl[mf][1]);
                }
            }
        }
    }
    __syncthreads();                      // all MMA done before smem reuse

    if (EPI == 0) {
        // ---- fp32 epilogue + deterministic BN partial stats ----
        float* Yb = Yf + (size_t)b * Cout * MPTS;
        const int prt = (blockIdx.x * 4 + warp_m) * 32 + blockIdx.z; // 0..2047
#pragma unroll
        for (int of = 0; of < OFR; ++of) {
            int o = o0 + warp_o * OW + of * 16 + (lane >> 2);
#pragma unroll
            for (int hf = 0; hf < 2; ++hf) {
                int oc = o + hf * 8;
                float bs = bias[oc];
                float s = 0.f, s2 = 0.f;
#pragma unroll
                for (int mf = 0; mf < 4; ++mf) {
                    int m = m0 + warp_m * 32 + mf * 8 + 2 * (lane & 3);
                    float v0 = acc[of][mf][2 * hf]     + bs;
                    float v1 = acc[of][mf][2 * hf + 1] + bs;
                    *(float2*)&Yb[(size_t)oc * MPTS + m] = make_float2(v0, v1);
                    s  += v0 + v1;
                    s2 += v0 * v0 + v1 * v1;
                }
                s  += __shfl_xor_sync(0xffffffffu, s, 1);
                s2 += __shfl_xor_sync(0xffffffffu, s2, 1);
                s  += __shfl_xor_sync(0xffffffffu, s, 2);
                s2 += __shfl_xor_sync(0xffffffffu, s2, 2);
                if ((lane & 3) == 0) {
                    part[(size_t)(2 * oc)     * 2048 + prt] = s;
                    part[(size_t)(2 * oc + 1) * 2048 + prt] = s2;
                }
            }
        }
    } else {
        // ---- split epilogue: smem transpose -> [b][m][c] fp16 H/L ----
        __half* SH = (__half*)smem;                 // 128 x 136
        __half* SL = SH + 128 * 136;
#pragma unroll
        for (int of = 0; of < OFR; ++of) {
            int orel0 = warp_o * OW + of * 16 + (lane >> 2);
#pragma unroll
            for (int hf = 0; hf < 2; ++hf) {
                int orel = orel0 + hf * 8;
                int o = o0 + orel;
                float bs = bias[o];
                float zv = (EPI == 2) ? zmod[(size_t)b * CW + o] : 0.f;
#pragma unroll
                for (int mf = 0; mf < 4; ++mf) {
                    int mrel = warp_m * 32 + mf * 8 + 2 * (lane & 3);
                    float v0 = acc[of][mf][2 * hf]     + bs;
                    float v1 = acc[of][mf][2 * hf + 1] + bs;
                    if (EPI == 1) { v0 = fmaxf(v0, 0.f); v1 = fmaxf(v1, 0.f); }
                    if (EPI == 2) {
                        v0 = zv * fminf(fmaxf(v0, -1.f), 1.f);
                        v1 = zv * fminf(fmaxf(v1, -1.f), 1.f);
                    }
                    __half h0 = __float2half_rn(v0), h1 = __float2half_rn(v1);
                    SH[mrel * 136 + orel]       = h0;
                    SH[(mrel + 1) * 136 + orel] = h1;
                    SL[mrel * 136 + orel]       = __float2half_rn(v0 - __half2float(h0));
                    SL[(mrel + 1) * 136 + orel] = __float2half_rn(v1 - __half2float(h1));
                }
            }
        }
        __syncthreads();
        for (int i = tid; i < 2048; i += 256) {
            int m = i >> 4, p = i & 15;
            size_t gb = ((size_t)b * MPTS + m0 + m) * Cout + o0 + p * 8;
            *(uint4*)(YH + gb) = *(uint4*)(SH + m * 136 + p * 8);
            *(uint4*)(YL + gb) = *(uint4*)(SL + m * 136 + p * 8);
        }
    }
}

// ---------------- BN finalize: partials -> folded affine (a, c) ------------
__global__ void bn_finalize_kernel(const float* __restrict__ part, int Cout,
                                   const float* __restrict__ g,
                                   const float* __restrict__ be,
                                   float* __restrict__ a_out,
                                   float* __restrict__ c_out)
{
    int o = blockIdx.x;
    const float* ps  = part + (size_t)(2 * o)     * 2048;
    const float* ps2 = part + (size_t)(2 * o + 1) * 2048;
    float s = 0.f, s2 = 0.f;
    for (int p = threadIdx.x; p < 2048; p += 256) {
        s  += ps[p];
        s2 += ps2[p];
    }
#pragma unroll
    for (int off = 16; off; off >>= 1) {
        s  += __shfl_down_sync(0xffffffffu, s,  off);
        s2 += __shfl_down_sync(0xffffffffu, s2, off);
    }
    __shared__ float sh[8], sh2[8];
    int w = threadIdx.x >> 5, l = threadIdx.x & 31;
    if (l == 0) { sh[w] = s; sh2[w] = s2; }
    __syncthreads();
    if (threadIdx.x < 8) {
        s = sh[threadIdx.x]; s2 = sh2[threadIdx.x];
#pragma unroll
        for (int off = 4; off; off >>= 1) {
            s  += __shfl_down_sync(0xffu, s,  off);
            s2 += __shfl_down_sync(0xffu, s2, off);
        }
        if (threadIdx.x == 0) {
            const float inv = 1.f / (float)(BATCH * MPTS);
            float mu  = s * inv;
            float var = s2 * inv - mu * mu;
            float aa  = g[o] * rsqrtf(var + 1e-5f);
            a_out[o] = aa;
            c_out[o] = be[o] - aa * mu;
        }
    }
}

// ---------------- 64->3 projection -> packed float4 (x,y,z,|p|^2) ----------
__global__ void out_kernel(const float* __restrict__ T3,
                           const float* __restrict__ w_out,
                           const float* __restrict__ b_out,
                           const float* __restrict__ a,
                           const float* __restrict__ c,
                           float4* __restrict__ pk)
{
    __shared__ float Ws[3][64];
    __shared__ float As[64], Cs[64];
    int tid = threadIdx.x;
    if (tid < 192) Ws[tid / 64][tid & 63] = w_out[tid];
    if (tid < 64) { As[tid] = a[tid]; Cs[tid] = c[tid]; }
    __syncthreads();

    int idx = blockIdx.x * blockDim.x + tid;
    int b = idx >> 11, m = idx & (MPTS - 1);
    const float* p = T3 + (size_t)b * 64 * MPTS + m;
    float a0 = b_out[0], a1 = b_out[1], a2 = b_out[2];
#pragma unroll 8
    for (int k = 0; k < 64; ++k) {
        float v = fmaxf(fmaf(As[k], p[(size_t)k * MPTS], Cs[k]), 0.f);
        a0 = fmaf(Ws[0][k], v, a0);
        a1 = fmaf(Ws[1][k], v, a1);
        a2 = fmaf(Ws[2][k], v, a2);
    }
    pk[idx] = make_float4(a0, a1, a2, a0 * a0 + a1 * a1 + a2 * a2);
}

// ---------------- kNN (K=8) sharpening filter (float4 smem, unroll 2) -------
__global__ __launch_bounds__(256, 2)
void graph_filter_kernel(const float4* __restrict__ pk_g,
                         float* __restrict__ out)
{
    __shared__ __align__(16) float4 pk[MPTS];
    int b = blockIdx.y;
    int tid = threadIdx.x;
    const float4* pb = pk_g + (size_t)b * MPTS;
    for (int i = tid; i < MPTS; i += 256)
        pk[i] = pb[i];
    __syncthreads();

    int p = blockIdx.x * 256 + tid;
    float4 me = pk[p];
    float nx = -2.f * me.x, ny = -2.f * me.y, nz = -2.f * me.z;

    float bd[8]; int bi[8];
#pragma unroll
    for (int j = 0; j < 8; ++j) { bd[j] = 3.4e38f; bi[j] = 0; }

    for (int n = 0; n < MPTS; n += 2) {
        float4 q0 = pk[n];
        float4 q1 = pk[n + 1];
        float d0 = fmaf(nx, q0.x, fmaf(ny, q0.y, fmaf(nz, q0.z, q0.w)));
        float d1 = fmaf(nx, q1.x, fmaf(ny, q1.y, fmaf(nz, q1.z, q1.w)));
        if (n != p && d0 < bd[7]) {
            bd[7] = d0; bi[7] = n;
#pragma unroll
            for (int j = 7; j > 0; --j)
                if (bd[j] < bd[j - 1]) {
                    float td = bd[j]; bd[j] = bd[j - 1]; bd[j - 1] = td;
                    int   ti = bi[j]; bi[j] = bi[j - 1]; bi[j - 1] = ti;
                }
        }
        if (n + 1 != p && d1 < bd[7]) {
            bd[7] = d1; bi[7] = n + 1;
#pragma unroll
            for (int j = 7; j > 0; --j)
                if (bd[j] < bd[j - 1]) {
                    float td = bd[j]; bd[j] = bd[j - 1]; bd[j - 1] = td;
                    int   ti = bi[j]; bi[j] = bi[j - 1]; bi[j - 1] = ti;
                }
        }
    }

    float mx = 0.f, my = 0.f, mz = 0.f;
#pragma unroll
    for (int j = 0; j < 8; ++j) {
        float4 q = pk[bi[j]];
        mx += q.x; my += q.y; mz += q.z;
    }
    const float k8 = 1.f / 8.f;
    float* ob = out + (size_t)b * 3 * MPTS;
    ob[p]            = 2.f * me.x - mx * k8;
    ob[MPTS + p]     = 2.f * me.y - my * k8;
    ob[2 * MPTS + p] = 2.f * me.z - mz * k8;
}

// ---------------------------------------------------------------------------
#define STAGE_OT(OT) ((2 * (OT) + 256) * 80)
#define SMEM_OT(OT)  (2 * STAGE_OT(OT))

extern "C" void kernel_launch(void* const* d_in, const int* in_sizes, int n_in,
                              void* d_out, int out_size)
{
    const float* z     = (const float*)d_in[0];
    const float* s     = (const float*)d_in[1];
    const float* w_m1  = (const float*)d_in[2];
    const float* b_m1  = (const float*)d_in[3];
    const float* w_m2  = (const float*)d_in[4];
    const float* b_m2  = (const float*)d_in[5];
    const float* w_out = (const float*)d_in[6];
    const float* b_out = (const float*)d_in[7];
    const float* w_c [4] = {(const float*)d_in[8],  (const float*)d_in[12],
                            (const float*)d_in[16], (const float*)d_in[20]};
    const float* b_c [4] = {(const float*)d_in[9],  (const float*)d_in[13],
                            (const float*)d_in[17], (const float*)d_in[21]};
    const float* g_c [4] = {(const float*)d_in[10], (const float*)d_in[14],
                            (const float*)d_in[18], (const float*)d_in[22]};
    const float* be_c[4] = {(const float*)d_in[11], (const float*)d_in[15],
                            (const float*)d_in[19], (const float*)d_in[23]};

    float *t0, *t1, *t2, *t3, *aff_a, *aff_c, *part;
    float4* pk;
    __half *xnH, *xnL, *y1H, *y1L, *y2H, *y2L, *WH, *WL;
    cudaGetSymbolAddress((void**)&t0,    g_t0);
    cudaGetSymbolAddress((void**)&t1,    g_t1);
    cudaGetSymbolAddress((void**)&t2,    g_t2);
    cudaGetSymbolAddress((void**)&t3,    g_t3);
    cudaGetSymbolAddress((void**)&pk,    g_pk);
    cudaGetSymbolAddress((void**)&aff_a, g_aff_a);
    cudaGetSymbolAddress((void**)&aff_c, g_aff_c);
    cudaGetSymbolAddress((void**)&part,  g_part);
    cudaGetSymbolAddress((void**)&xnH,   g_xnH);
    cudaGetSymbolAddress((void**)&xnL,   g_xnL);
    cudaGetSymbolAddress((void**)&y1H,   g_y1H);
    cudaGetSymbolAddress((void**)&y1L,   g_y1L);
    cudaGetSymbolAddress((void**)&y2H,   g_y2H);
    cudaGetSymbolAddress((void**)&y2L,   g_y2L);
    cudaGetSymbolAddress((void**)&WH,    g_WH);
    cudaGetSymbolAddress((void**)&WL,    g_WL);

    cudaFuncSetAttribute(gemm_mma<128, 0, 1>, cudaFuncAttributeMaxDynamicSharedMemorySize, SMEM_OT(128));
    cudaFuncSetAttribute(gemm_mma<128, 0, 2>, cudaFuncAttributeMaxDynamicSharedMemorySize, SMEM_OT(128));
    cudaFuncSetAttribute(gemm_mma<128, 0, 0>, cudaFuncAttributeMaxDynamicSharedMemorySize, SMEM_OT(128));
    cudaFuncSetAttribute(gemm_mma<128, 1, 0>, cudaFuncAttributeMaxDynamicSharedMemorySize, SMEM_OT(128));
    cudaFuncSetAttribute(gemm_mma<64, 1, 0>,  cudaFuncAttributeMaxDynamicSharedMemorySize, SMEM_OT(64));

    // 0) fused prep: weight splits + sample normalize/split
    prep_kernel<<<2480, 256>>>(w_m1, w_m2, w_c[0], w_c[1], w_c[2], w_c[3],
                               WH, WL, s, xnH, xnL);

    // 1) map_samples1: 16 -> 256, relu, split out
    gemm_mma<128, 0, 1><<<dim3(MPTS / 128, 2, BATCH), 256, SMEM_OT(128)>>>(
        xnH, xnL, nullptr, WH + WO_1, WL + WO_1, b_m1,
        nullptr, y1H, y1L, 16, 256, nullptr, nullptr, nullptr, nullptr);

    // 2) map_samples2: 256 -> 512, z*clip, split out
    gemm_mma<128, 0, 2><<<dim3(MPTS / 128, 4, BATCH), 256, SMEM_OT(128)>>>(
        y1H, y1L, nullptr, WH + WO_2, WL + WO_2, b_m2,
        nullptr, y2H, y2L, 256, 512, nullptr, nullptr, z, nullptr);

    // 3) conv block 0: 512 -> 512, fp32 out + fused stats
    gemm_mma<128, 0, 0><<<dim3(MPTS / 128, 4, BATCH), 256, SMEM_OT(128)>>>(
        y2H, y2L, nullptr, WH + WO_3, WL + WO_3, b_c[0],
        t0, nullptr, nullptr, 512, 512, nullptr, nullptr, nullptr, part);
    bn_finalize_kernel<<<512, 256>>>(part, 512, g_c[0], be_c[0], aff_a, aff_c);

    // 4) conv block 1: relu(bn(t0)) -> 256
    gemm_mma<128, 1, 0><<<dim3(MPTS / 128, 2, BATCH), 256, SMEM_OT(128)>>>(
        nullptr, nullptr, t0, WH + WO_4, WL + WO_4, b_c[1],
        t1, nullptr, nullptr, 512, 256, aff_a, aff_c, nullptr, part);
    bn_finalize_kernel<<<256, 256>>>(part, 256, g_c[1], be_c[1],
                                     aff_a + 512, aff_c + 512);

    // 5) conv block 2: -> 128
    gemm_mma<128, 1, 0><<<dim3(MPTS / 128, 1, BATCH), 256, SMEM_OT(128)>>>(
        nullptr, nullptr, t1, WH + WO_5, WL + WO_5, b_c[2],
        t2, nullptr, nullptr, 256, 128, aff_a + 512, aff_c + 512, nullptr, part);
    bn_finalize_kernel<<<128, 256>>>(part, 128, g_c[2], be_c[2],
                                     aff_a + 1024, aff_c + 1024);

    // 6) conv block 3: -> 64
    gemm_mma<64, 1, 0><<<dim3(MPTS / 128, 1, BATCH), 256, SMEM_OT(64)>>>(
        nullptr, nullptr, t2, WH + WO_6, WL + WO_6, b_c[3],
        t3, nullptr, nullptr, 128, 64, aff_a + 1024, aff_c + 1024, nullptr, part);
    bn_finalize_kernel<<<64, 256>>>(part, 64, g_c[3], be_c[3],
                                    aff_a + 1536, aff_c + 1536);

    // 7) output projection 64 -> 3 -> packed float4
    out_kernel<<<(BATCH * MPTS) / 256, 256>>>(t3, w_out, b_out,
                                              aff_a + 1536, aff_c + 1536, pk);

    // 8) graph sharpening filter
    graph_filter_kernel<<<dim3(MPTS / 256, BATCH), 256>>>(pk, (float*)d_out);
}